// round 9
// baseline (speedup 1.0000x reference)
#include <cuda_runtime.h>
#include <cuda_fp16.h>

// ===========================================================================
// B=16, N=1024, D=512, H=8, dk=64. ROWS=16384.
// HMMA (mma.sync m16n8k16), fp32 accum, split-fp16 where precision needs it:
//   QK proj: fused 3-term (Xh*Wh + Xl*Wh + Xh*Wl) sharing staged tiles
//   S      : 2-term (Qh*Kh + Ql*Kh), online softmax in fused flash kernel
//   V proj : 1-term, out proj: 1-term, PV: V-hi only
// ===========================================================================
#define ROWS 16384
#define PADK 72
#define TILEB (128 * PADK * 2)          // 18432 bytes per matrix tile
#define G1_SMEM (4 * TILEB)             // generic: 2 slots x (A+B)
#define QK_SLOT (4 * TILEB)             // Ah|Al|Bh|Bl
#define QK_SMEM (2 * QK_SLOT)           // 147456

#define XSTR  ((long long)ROWS * 512)
#define WSTR  (524288LL)
#define QKSTR ((long long)ROWS * 1024)
#define HSTR  ((long long)ROWS * 1024)
#define OSTR  ((long long)ROWS * 512)

// Fused attention smem layout (bytes)
#define NKT   16
#define OFF_Q  0
#define OFF_KV 36864
#define KVBUF  27648
#define OFF_S  92160
#define OFF_P  125952
#define OFF_M  144384
#define OFF_L  144896
#define OFF_F  145408
#define FA_SMEM 145920

// ---------------------------------------------------------------------------
// Static device scratch
// ---------------------------------------------------------------------------
__device__ __half g_Wqkh[2][524288], g_Wqkl[2][524288];
__device__ __half g_Wvh [2][524288];
__device__ __half g_Woh [2][524288];
__device__ __half g_Xh  [2][8388608], g_Xl[2][8388608];
__device__ __half g_QKh [2][16777216], g_QKl[2][16777216];
__device__ __half g_Vth [2][16777216];
__device__ __half g_H   [2][16777216];

// ---------------------------------------------------------------------------
// PTX helpers
// ---------------------------------------------------------------------------
__device__ __forceinline__ unsigned smem_u32(const void* p) {
    unsigned a;
    asm("{ .reg .u64 t; cvta.to.shared.u64 t, %1; cvt.u32.u64 %0, t; }"
        : "=r"(a) : "l"(p));
    return a;
}
__device__ __forceinline__ void cpasync16(unsigned s, const void* g) {
    asm volatile("cp.async.cg.shared.global [%0], [%1], 16;" :: "r"(s), "l"(g));
}
__device__ __forceinline__ void cp_commit() {
    asm volatile("cp.async.commit_group;" ::: "memory");
}
__device__ __forceinline__ void cp_wait0() {
    asm volatile("cp.async.wait_group 0;" ::: "memory");
}
__device__ __forceinline__ void ldm4(unsigned& r0, unsigned& r1, unsigned& r2,
                                     unsigned& r3, unsigned a) {
    asm volatile("ldmatrix.sync.aligned.m8n8.x4.shared.b16 {%0,%1,%2,%3}, [%4];"
                 : "=r"(r0), "=r"(r1), "=r"(r2), "=r"(r3) : "r"(a));
}
__device__ __forceinline__ void mma16816(float* c, const unsigned* a,
                                         const unsigned* b) {
    asm volatile(
        "mma.sync.aligned.m16n8k16.row.col.f32.f16.f16.f32 "
        "{%0,%1,%2,%3}, {%4,%5,%6,%7}, {%8,%9}, {%0,%1,%2,%3};"
        : "+f"(c[0]), "+f"(c[1]), "+f"(c[2]), "+f"(c[3])
        : "r"(a[0]), "r"(a[1]), "r"(a[2]), "r"(a[3]), "r"(b[0]), "r"(b[1]));
}
__device__ __forceinline__ void split2(float v0, float v1, __half2& hi, __half2& lo) {
    __half h0 = __float2half_rn(v0), h1 = __float2half_rn(v1);
    __half l0 = __float2half_rn(v0 - __half2float(h0));
    __half l1 = __float2half_rn(v1 - __half2float(h1));
    hi = __halves2half2(h0, h1);
    lo = __halves2half2(l0, l1);
}

// ---------------------------------------------------------------------------
// Fused 3-term QK projection: C = Xh*Wh^T + Xl*Wh^T + Xh*Wl^T.
// Block 128x128, 512 threads, 4x4 warps (32x32 warp tiles), K=512.
// Per K-chunk stages Ah|Al|Bh|Bl once; 24 MMAs per ks from 8 ldmatrix.
// Pair epilogue -> QKh/QKl. blockIdx.z = stream.
// ---------------------------------------------------------------------------
__global__ __launch_bounds__(512)
void hgemm_qk(const __half* __restrict__ Ah_, const __half* __restrict__ Al_,
              const __half* __restrict__ Bh_, const __half* __restrict__ Bl_,
              __half* __restrict__ Ch_, __half* __restrict__ Cl_) {
    extern __shared__ __align__(16) char smem[];
    const unsigned sbase = smem_u32(smem);

    const int tid = threadIdx.x;
    const int wid = tid >> 5, lane = tid & 31;
    const int wm = wid & 3, wn = wid >> 2;
    const int zb = (int)blockIdx.z;

    const long long aoff = (long long)zb * XSTR + (long long)(blockIdx.y * 128) * 512;
    const long long boff = (long long)zb * WSTR + (long long)(blockIdx.x * 128) * 512;
    const __half* Ah = Ah_ + aoff;
    const __half* Al = Al_ + aoff;
    const __half* Bh = Bh_ + boff;
    const __half* Bl = Bl_ + boff;

    const int r0c = tid >> 3, s0c = tid & 7;
    const int r1c = r0c + 64;
    const int tr0 = r0c * 512 + s0c * 8, tr1 = r1c * 512 + s0c * 8;
    const unsigned so0 = (unsigned)(r0c * PADK + s0c * 8) * 2;
    const unsigned so1 = (unsigned)(r1c * PADK + s0c * 8) * 2;

#define QK_LOAD(kt, bf)                                                       \
    do {                                                                      \
        unsigned sl = sbase + (bf) * QK_SLOT;                                 \
        const __half* p;                                                      \
        p = Ah + (kt) * 64;                                                   \
        cpasync16(sl + so0, p + tr0);  cpasync16(sl + so1, p + tr1);          \
        p = Al + (kt) * 64;                                                   \
        cpasync16(sl + TILEB + so0, p + tr0);                                 \
        cpasync16(sl + TILEB + so1, p + tr1);                                 \
        p = Bh + (kt) * 64;                                                   \
        cpasync16(sl + 2 * TILEB + so0, p + tr0);                             \
        cpasync16(sl + 2 * TILEB + so1, p + tr1);                             \
        p = Bl + (kt) * 64;                                                   \
        cpasync16(sl + 3 * TILEB + so0, p + tr0);                             \
        cpasync16(sl + 3 * TILEB + so1, p + tr1);                             \
        cp_commit();                                                          \
    } while (0)

    QK_LOAD(0, 0);

    float acc[2][4][4];
#pragma unroll
    for (int i = 0; i < 2; i++)
#pragma unroll
        for (int j = 0; j < 4; j++)
#pragma unroll
            for (int k = 0; k < 4; k++) acc[i][j][k] = 0.f;

    const int sub = lane >> 3, r8 = lane & 7;

    for (int g = 0; g < 8; g++) {
        const int bf = g & 1;
        cp_wait0();
        __syncthreads();
        if (g + 1 < 8) QK_LOAD(g + 1, bf ^ 1);

        const unsigned sl = sbase + bf * QK_SLOT;
#pragma unroll
        for (int ks = 0; ks < 4; ks++) {
            const int k0 = ks * 16;
            unsigned ah[2][4], al[2][4];
#pragma unroll
            for (int mi = 0; mi < 2; mi++) {
                unsigned off = (unsigned)((wm * 32 + mi * 16 + r8 + (sub & 1) * 8) * PADK +
                                          k0 + (sub >> 1) * 8) * 2;
                ldm4(ah[mi][0], ah[mi][1], ah[mi][2], ah[mi][3], sl + off);
                ldm4(al[mi][0], al[mi][1], al[mi][2], al[mi][3], sl + TILEB + off);
            }
            unsigned bh[4][2], bl[4][2];
#pragma unroll
            for (int np = 0; np < 2; np++) {
                unsigned off = (unsigned)((wn * 32 + np * 16 + r8 + (sub >> 1) * 8) * PADK +
                                          k0 + (sub & 1) * 8) * 2;
                unsigned q0, q1, q2, q3;
                ldm4(q0, q1, q2, q3, sl + 2 * TILEB + off);
                bh[np * 2][0] = q0; bh[np * 2][1] = q1;
                bh[np * 2 + 1][0] = q2; bh[np * 2 + 1][1] = q3;
                ldm4(q0, q1, q2, q3, sl + 3 * TILEB + off);
                bl[np * 2][0] = q0; bl[np * 2][1] = q1;
                bl[np * 2 + 1][0] = q2; bl[np * 2 + 1][1] = q3;
            }
#pragma unroll
            for (int mi = 0; mi < 2; mi++)
#pragma unroll
                for (int ni = 0; ni < 4; ni++) {
                    mma16816(acc[mi][ni], ah[mi], bh[ni]);
                    mma16816(acc[mi][ni], al[mi], bh[ni]);
                    mma16816(acc[mi][ni], ah[mi], bl[ni]);
                }
        }
        __syncthreads();
    }
#undef QK_LOAD

    // pair epilogue -> Ch/Cl
    const int trow = lane >> 2, tcol = (lane & 3) * 2;
    const long long coff = (long long)zb * QKSTR;
    __half* Ch = Ch_ + coff;
    __half* Cl = Cl_ + coff;
#pragma unroll
    for (int mi = 0; mi < 2; mi++) {
#pragma unroll
        for (int ni = 0; ni < 4; ni++) {
            int rg = blockIdx.y * 128 + wm * 32 + mi * 16 + trow;
            int cg = blockIdx.x * 128 + wn * 32 + ni * 8 + tcol;
            float* ac = acc[mi][ni];
            __half2 h, l;
            size_t o0 = (size_t)rg * 1024 + cg;
            size_t o1 = (size_t)(rg + 8) * 1024 + cg;
            split2(ac[0], ac[1], h, l);
            *(__half2*)(Ch + o0) = h;
            *(__half2*)(Cl + o0) = l;
            split2(ac[2], ac[3], h, l);
            *(__half2*)(Ch + o1) = h;
            *(__half2*)(Cl + o1) = l;
        }
    }
}

// ---------------------------------------------------------------------------
// Generic 1-term HMMA GEMM with ks-level fragment software pipelining.
// C = A(M,K)*B(N,K)^T. modes: 1 fp32 out | 7 fp16 out + V row remap.
// blockIdx.z = stream (strides sAb/sBb/sCb; mode 7 halfoff*zb).
// ---------------------------------------------------------------------------
__global__ __launch_bounds__(512)
void hgemm1(const __half* __restrict__ A, long long sAb, int lda,
            const __half* __restrict__ B, long long sBb, int ldb,
            void* __restrict__ C0, long long sCb, int ldc,
            int K, int mode, int halfoff) {
    extern __shared__ __align__(16) char smem[];
    const unsigned smA = smem_u32(smem);
    const unsigned smB = smA + 2 * TILEB;

    const int tid = threadIdx.x;
    const int wid = tid >> 5, lane = tid & 31;
    const int wm = wid & 3, wn = wid >> 2;
    const int zb = (int)blockIdx.z;

    const __half* Ab = A + (long long)zb * sAb + (long long)(blockIdx.y * 128) * lda;
    const __half* Bb = B + (long long)zb * sBb + (long long)(blockIdx.x * 128) * ldb;

    const int r0c = tid >> 3, s0c = tid & 7;
    const int r1c = r0c + 64;
    const int trA0 = r0c * lda + s0c * 8, trA1 = r1c * lda + s0c * 8;
    const int trB0 = r0c * ldb + s0c * 8, trB1 = r1c * ldb + s0c * 8;
    const unsigned so0 = (unsigned)(r0c * PADK + s0c * 8) * 2;
    const unsigned so1 = (unsigned)(r1c * PADK + s0c * 8) * 2;

    const int T = K >> 6;

#define G1_LOAD(kt, bf)                                                       \
    do {                                                                      \
        const __half* ap = Ab + (kt) * 64;                                    \
        const __half* bp = Bb + (kt) * 64;                                    \
        cpasync16(smA + (bf) * TILEB + so0, ap + trA0);                       \
        cpasync16(smA + (bf) * TILEB + so1, ap + trA1);                       \
        cpasync16(smB + (bf) * TILEB + so0, bp + trB0);                       \
        cpasync16(smB + (bf) * TILEB + so1, bp + trB1);                       \
        cp_commit();                                                          \
    } while (0)

    G1_LOAD(0, 0);

    float acc[2][4][4];
#pragma unroll
    for (int i = 0; i < 2; i++)
#pragma unroll
        for (int j = 0; j < 4; j++)
#pragma unroll
            for (int k = 0; k < 4; k++) acc[i][j][k] = 0.f;

    const int sub = lane >> 3, r8 = lane & 7;
    const unsigned aoffbase = (unsigned)((wm * 32 + r8 + (sub & 1) * 8) * PADK +
                                         (sub >> 1) * 8) * 2;
    const unsigned boffbase = (unsigned)((wn * 32 + r8 + (sub >> 1) * 8) * PADK +
                                         (sub & 1) * 8) * 2;

    for (int g = 0; g < T; g++) {
        const int bf = g & 1;
        cp_wait0();
        __syncthreads();
        if (g + 1 < T) G1_LOAD(g + 1, bf ^ 1);

        const unsigned ab = smA + bf * TILEB;
        const unsigned bb = smB + bf * TILEB;

        unsigned a[2][2][4], b[2][4][2];
        // preload ks=0 fragments
#pragma unroll
        for (int mi = 0; mi < 2; mi++)
            ldm4(a[0][mi][0], a[0][mi][1], a[0][mi][2], a[0][mi][3],
                 ab + aoffbase + (unsigned)(mi * 16 * PADK) * 2);
#pragma unroll
        for (int np = 0; np < 2; np++) {
            unsigned q0, q1, q2, q3;
            ldm4(q0, q1, q2, q3, bb + boffbase + (unsigned)(np * 16 * PADK) * 2);
            b[0][np * 2][0] = q0; b[0][np * 2][1] = q1;
            b[0][np * 2 + 1][0] = q2; b[0][np * 2 + 1][1] = q3;
        }

#pragma unroll
        for (int ks = 0; ks < 4; ks++) {
            const int cur = ks & 1, nxt = cur ^ 1;
            if (ks < 3) {
                const unsigned kadd = (unsigned)((ks + 1) * 16) * 2;
#pragma unroll
                for (int mi = 0; mi < 2; mi++)
                    ldm4(a[nxt][mi][0], a[nxt][mi][1], a[nxt][mi][2], a[nxt][mi][3],
                         ab + aoffbase + kadd + (unsigned)(mi * 16 * PADK) * 2);
#pragma unroll
                for (int np = 0; np < 2; np++) {
                    unsigned q0, q1, q2, q3;
                    ldm4(q0, q1, q2, q3,
                         bb + boffbase + kadd + (unsigned)(np * 16 * PADK) * 2);
                    b[nxt][np * 2][0] = q0; b[nxt][np * 2][1] = q1;
                    b[nxt][np * 2 + 1][0] = q2; b[nxt][np * 2 + 1][1] = q3;
                }
            }
#pragma unroll
            for (int mi = 0; mi < 2; mi++)
#pragma unroll
                for (int ni = 0; ni < 4; ni++)
                    mma16816(acc[mi][ni], a[cur][mi], b[cur][ni]);
        }
        __syncthreads();
    }
#undef G1_LOAD

    const int trow = lane >> 2, tcol = (lane & 3) * 2;
    const long long coff = (long long)zb * sCb;

#pragma unroll
    for (int mi = 0; mi < 2; mi++) {
#pragma unroll
        for (int ni = 0; ni < 4; ni++) {
            int rg = blockIdx.y * 128 + wm * 32 + mi * 16 + trow;
            int cg = blockIdx.x * 128 + wn * 32 + ni * 8 + tcol;
            float* ac = acc[mi][ni];
            if (mode == 1) {
                float* p0 = (float*)C0 + coff + (size_t)rg * ldc + cg;
                float* p1 = (float*)C0 + coff + (size_t)(rg + 8) * ldc + cg;
                *(float2*)p0 = make_float2(ac[0], ac[1]);
                *(float2*)p1 = make_float2(ac[2], ac[3]);
            } else {  // mode 7: single fp16 out + V row remap (halfoff * zb)
                int ho = halfoff * zb;
                int ra = ((rg >> 6) << 7) + (rg & 63) + ho;
                int rb0 = rg + 8;
                int rb = ((rb0 >> 6) << 7) + (rb0 & 63) + ho;
                *(__half2*)((__half*)C0 + (size_t)ra * ldc + cg) =
                    __floats2half2_rn(ac[0], ac[1]);
                *(__half2*)((__half*)C0 + (size_t)rb * ldc + cg) =
                    __floats2half2_rn(ac[2], ac[3]);
            }
        }
    }
}

// ---------------------------------------------------------------------------
// Fused flash attention, both softmax streams in one launch (blockIdx.z).
// S = Qh*Kh^T + Ql*Kh^T (Q pre-scaled 1/8), online softmax, O += P * Vh^T.
// ---------------------------------------------------------------------------
__global__ __launch_bounds__(512)
void flash_attn(const __half* __restrict__ QKhB, const __half* __restrict__ QKlB,
                const __half* __restrict__ VhB,
                __half* __restrict__ H0B, __half* __restrict__ H1B) {
    extern __shared__ __align__(16) char smem[];
    const unsigned sb = smem_u32(smem);
    float* Sf  = (float*)(smem + OFF_S);
    __half* Pm = (__half*)(smem + OFF_P);
    float* smM = (float*)(smem + OFF_M);
    float* smL = (float*)(smem + OFF_L);
    float* smF = (float*)(smem + OFF_F);

    const int tid = threadIdx.x, wid = tid >> 5, lane = tid & 31;
    const int wm = wid & 3, wn = wid >> 2;
    const int sub = lane >> 3, r8 = lane & 7;
    const int trow = lane >> 2, tcol = (lane & 3) * 2;
    const int qt = blockIdx.x, z = blockIdx.y;
    const int h = z >> 4, b = z & 15;
    const int s = blockIdx.z;

    const __half* QKh = QKhB + (size_t)s * QKSTR;
    const __half* QKl = QKlB + (size_t)s * QKSTR;
    const __half* Vh  = VhB  + (size_t)s * 16777216;
    __half* C0 = H0B + s * 64;
    __half* C1 = H1B + s * 64;

    if (tid < 128) { smM[tid] = -1e30f; smL[tid] = 0.f; }

    {
        const size_t rbase = (size_t)(b << 10) + qt * 128;
        int c0 = tid, c1 = tid + 512;
        int r0 = c0 >> 3, s0 = c0 & 7, r1 = c1 >> 3, s1 = c1 & 7;
        int col0 = h * 64 + s0 * 8, col1 = h * 64 + s1 * 8;
        cpasync16(sb + OFF_Q + (unsigned)(r0 * 72 + s0 * 8) * 2,
                  QKh + (rbase + r0) * 1024 + col0);
        cpasync16(sb + OFF_Q + (unsigned)(r1 * 72 + s1 * 8) * 2,
                  QKh + (rbase + r1) * 1024 + col1);
        cpasync16(sb + OFF_Q + 18432 + (unsigned)(r0 * 72 + s0 * 8) * 2,
                  QKl + (rbase + r0) * 1024 + col0);
        cpasync16(sb + OFF_Q + 18432 + (unsigned)(r1 * 72 + s1 * 8) * 2,
                  QKl + (rbase + r1) * 1024 + col1);
    }

#define LOAD_KV(kt, bi)                                                       \
    do {                                                                      \
        int rr = tid >> 3, ss = tid & 7;                                      \
        size_t gr = (size_t)(b << 10) + (kt) * 64 + rr;                       \
        unsigned sof = (unsigned)(rr * 72 + ss * 8) * 2;                      \
        cpasync16(sb + OFF_KV + (bi) * KVBUF + sof,                           \
                  QKh + gr * 1024 + 512 + h * 64 + ss * 8);                   \
        int v0 = tid, v1 = tid + 512;                                         \
        int vr0 = v0 >> 3, vs0 = v0 & 7, vr1 = v1 >> 3, vs1 = v1 & 7;         \
        size_t vcb = (size_t)(b << 10) + (kt) * 64;                           \
        cpasync16(sb + OFF_KV + (bi) * KVBUF + 9216 +                         \
                      (unsigned)(vr0 * 72 + vs0 * 8) * 2,                     \
                  Vh + (size_t)(h * 128 + vr0) * 16384 + vcb + vs0 * 8);      \
        cpasync16(sb + OFF_KV + (bi) * KVBUF + 9216 +                         \
                      (unsigned)(vr1 * 72 + vs1 * 8) * 2,                     \
                  Vh + (size_t)(h * 128 + vr1) * 16384 + vcb + vs1 * 8);      \
        cp_commit();                                                          \
    } while (0)

    LOAD_KV(0, 0);
    cp_wait0();

    float O[2][4][4] = {};

    for (int kt = 0; kt < NKT; kt++) {
        const int bi = kt & 1;
        if (kt) cp_wait0();
        __syncthreads();
        if (kt + 1 < NKT) LOAD_KV(kt + 1, bi ^ 1);

        const unsigned Kh = sb + OFF_KV + bi * KVBUF;
        const unsigned Vb = Kh + 9216;

        float acc[2][2][4] = {};
#pragma unroll
        for (int ks = 0; ks < 4; ks++) {
            const int k0 = ks * 16;
            unsigned ah[2][4], al[2][4];
#pragma unroll
            for (int mi = 0; mi < 2; mi++) {
                unsigned off = (unsigned)((wm * 32 + mi * 16 + r8 + (sub & 1) * 8) * 72 +
                                          k0 + (sub >> 1) * 8) * 2;
                ldm4(ah[mi][0], ah[mi][1], ah[mi][2], ah[mi][3], sb + OFF_Q + off);
                ldm4(al[mi][0], al[mi][1], al[mi][2], al[mi][3],
                     sb + OFF_Q + 18432 + off);
            }
            unsigned bh[2][2];
            {
                unsigned off = (unsigned)((wn * 16 + r8 + (sub >> 1) * 8) * 72 +
                                          k0 + (sub & 1) * 8) * 2;
                unsigned q0, q1, q2, q3;
                ldm4(q0, q1, q2, q3, Kh + off);
                bh[0][0] = q0; bh[0][1] = q1; bh[1][0] = q2; bh[1][1] = q3;
            }
#pragma unroll
            for (int mi = 0; mi < 2; mi++)
#pragma unroll
                for (int nf = 0; nf < 2; nf++) {
                    mma16816(acc[mi][nf], ah[mi], bh[nf]);
                    mma16816(acc[mi][nf], al[mi], bh[nf]);
                }
        }
#pragma unroll
        for (int mi = 0; mi < 2; mi++)
#pragma unroll
            for (int nf = 0; nf < 2; nf++) {
                int r0 = wm * 32 + mi * 16 + trow;
                int col = wn * 16 + nf * 8 + tcol;
                *(float2*)&Sf[r0 * 66 + col] =
                    make_float2(acc[mi][nf][0], acc[mi][nf][1]);
                *(float2*)&Sf[(r0 + 8) * 66 + col] =
                    make_float2(acc[mi][nf][2], acc[mi][nf][3]);
            }
        __syncthreads();

        {
            int r = tid >> 2, seg = tid & 3;
            float vals[16];
            float* bp = &Sf[r * 66 + seg * 16];
#pragma unroll
            for (int i = 0; i < 8; i++) {
                float2 t2 = *(float2*)(bp + 2 * i);
                vals[2 * i] = t2.x; vals[2 * i + 1] = t2.y;
            }
            float mt = vals[0];
#pragma unroll
            for (int i = 1; i < 16; i++) mt = fmaxf(mt, vals[i]);
            mt = fmaxf(mt, __shfl_xor_sync(~0u, mt, 1));
            mt = fmaxf(mt, __shfl_xor_sync(~0u, mt, 2));
            float mo = smM[r];
            float mn = fmaxf(mo, mt);
            float f = __expf(mo - mn);
            float sum = 0.f;
            __half* pp = &Pm[r * 72 + seg * 16];
#pragma unroll
            for (int i = 0; i < 8; i++) {
                float e0 = __expf(vals[2 * i] - mn);
                float e1 = __expf(vals[2 * i + 1] - mn);
                *(__half2*)(pp + 2 * i) = __floats2half2_rn(e0, e1);
                sum += e0 + e1;
            }
            sum += __shfl_xor_sync(~0u, sum, 1);
            sum += __shfl_xor_sync(~0u, sum, 2);
            if (seg == 0) {
                smM[r] = mn;
                smL[r] = smL[r] * f + sum;
                smF[r] = f;
            }
        }
        __syncthreads();

#pragma unroll
        for (int mi = 0; mi < 2; mi++) {
            float f0 = smF[wm * 32 + mi * 16 + trow];
            float f1 = smF[wm * 32 + mi * 16 + trow + 8];
#pragma unroll
            for (int nf = 0; nf < 4; nf++) {
                O[mi][nf][0] *= f0; O[mi][nf][1] *= f0;
                O[mi][nf][2] *= f1; O[mi][nf][3] *= f1;
            }
        }
#pragma unroll
        for (int ks = 0; ks < 4; ks++) {
            const int k0 = ks * 16;
            unsigned aP[2][4];
#pragma unroll
            for (int mi = 0; mi < 2; mi++) {
                unsigned off = (unsigned)((wm * 32 + mi * 16 + r8 + (sub & 1) * 8) * 72 +
                                          k0 + (sub >> 1) * 8) * 2;
                ldm4(aP[mi][0], aP[mi][1], aP[mi][2], aP[mi][3], sb + OFF_P + off);
            }
            unsigned bV[4][2];
#pragma unroll
            for (int np = 0; np < 2; np++) {
                unsigned off = (unsigned)((wn * 32 + np * 16 + r8 + (sub >> 1) * 8) * 72 +
                                          k0 + (sub & 1) * 8) * 2;
                unsigned q0, q1, q2, q3;
                ldm4(q0, q1, q2, q3, Vb + off);
                bV[np * 2][0] = q0; bV[np * 2][1] = q1;
                bV[np * 2 + 1][0] = q2; bV[np * 2 + 1][1] = q3;
            }
#pragma unroll
            for (int mi = 0; mi < 2; mi++)
#pragma unroll
                for (int nf = 0; nf < 4; nf++)
                    mma16816(O[mi][nf], aP[mi], bV[nf]);
        }
    }
#undef LOAD_KV

    const long long coff = 128LL * h + 1048576LL * b;
#pragma unroll
    for (int mi = 0; mi < 2; mi++) {
        int r0 = wm * 32 + mi * 16 + trow;
        float inv0 = 1.f / smL[r0], inv1 = 1.f / smL[r0 + 8];
        int rg0 = qt * 128 + r0, rg1 = rg0 + 8;
#pragma unroll
        for (int nf = 0; nf < 4; nf++) {
            int cg = wn * 32 + nf * 8 + tcol;
            __half* base = (cg < 64) ? C0 : C1;
            int cl = cg & 63;
            *(__half2*)(base + coff + (size_t)rg0 * 1024 + cl) =
                __floats2half2_rn(O[mi][nf][0] * inv0, O[mi][nf][1] * inv0);
            *(__half2*)(base + coff + (size_t)rg1 * 1024 + cl) =
                __floats2half2_rn(O[mi][nf][2] * inv1, O[mi][nf][3] * inv1);
        }
    }
}

// ---------------------------------------------------------------------------
// Fused weight prep: blockIdx.y = task (0/1 qk n/p, 2/3 v n/p, 4/5 wo n/p)
// ---------------------------------------------------------------------------
__global__ void prep_w(const float* __restrict__ Wqn, const float* __restrict__ Wkn,
                       const float* __restrict__ Wqp, const float* __restrict__ Wkp,
                       const float* __restrict__ Wvn, const float* __restrict__ Wvp,
                       const float* __restrict__ Won, const float* __restrict__ Wop,
                       __half* __restrict__ Wqkh, __half* __restrict__ Wqkl,
                       __half* __restrict__ Wvh, __half* __restrict__ Woh) {
    int idx = blockIdx.x * blockDim.x + threadIdx.x;
    if (idx >= 524288) return;
    int task = blockIdx.y;
    int st = task & 1;
    if (task < 2) {
        const float* Wq = st ? Wqp : Wqn;
        const float* Wk = st ? Wkp : Wkn;
        int j = idx >> 9, d = idx & 511;
        int jj = j & 511;
        float v;
        if (j < 512)
            v = Wq[((size_t)((jj >> 6) * 512 + d)) * 64 + (jj & 63)] * 0.125f;
        else
            v = Wk[((size_t)((jj >> 6) * 512 + d)) * 64 + (jj & 63)];
        __half h = __float2half_rn(v);
        Wqkh[(size_t)st * WSTR + idx] = h;
        Wqkl[(size_t)st * WSTR + idx] = __float2half_rn(v - __half2float(h));
    } else if (task < 4) {
        const float* Wv = st ? Wvp : Wvn;
        int j = idx >> 9, d = idx & 511;
        Wvh[(size_t)st * WSTR + idx] =
            __float2half_rn(Wv[((size_t)((j >> 6) * 512 + d)) * 64 + (j & 63)]);
    } else {
        const float* Wo = st ? Wop : Won;
        int e = idx >> 10, j = idx & 1023;
        Woh[(size_t)st * WSTR + idx] = __float2half_rn(Wo[(size_t)j * 512 + e]);
    }
}

__global__ void cvt_pair(const float* __restrict__ Xn, const float* __restrict__ Xp,
                         __half* __restrict__ Yh, __half* __restrict__ Yl) {
    int i = blockIdx.x * blockDim.x + threadIdx.x;
    if (i >= ROWS * 512 / 4) return;
    int st = blockIdx.y;
    const float* X = st ? Xp : Xn;
    float4 v = ((const float4*)X)[i];
    __half2 h0, l0, h1, l1;
    split2(v.x, v.y, h0, l0);
    split2(v.z, v.w, h1, l1);
    uint2 uh, ul;
    uh.x = *reinterpret_cast<unsigned*>(&h0);
    uh.y = *reinterpret_cast<unsigned*>(&h1);
    ul.x = *reinterpret_cast<unsigned*>(&l0);
    ul.y = *reinterpret_cast<unsigned*>(&l1);
    ((uint2*)(Yh + (size_t)st * XSTR))[i] = uh;
    ((uint2*)(Yl + (size_t)st * XSTR))[i] = ul;
}

// ---------------------------------------------------------------------------
// Host launcher: 6 kernel launches
// ---------------------------------------------------------------------------
extern "C" void kernel_launch(void* const* d_in, const int* in_sizes, int n_in,
                              void* d_out, int out_size) {
    const float* Xn  = (const float*)d_in[0];
    const float* Xp  = (const float*)d_in[1];
    const float* Wqn = (const float*)d_in[2];
    const float* Wqp = (const float*)d_in[3];
    const float* Wkn = (const float*)d_in[4];
    const float* Wkp = (const float*)d_in[5];
    const float* Wvn = (const float*)d_in[6];
    const float* Wvp = (const float*)d_in[7];
    const float* Won = (const float*)d_in[8];
    const float* Wop = (const float*)d_in[9];
    float* out = (float*)d_out;

    __half *Wqkh, *Wqkl, *Wvh, *Woh, *Xh, *Xl, *QKh, *QKl, *Vth, *H;
    cudaGetSymbolAddress((void**)&Wqkh, g_Wqkh);
    cudaGetSymbolAddress((void**)&Wqkl, g_Wqkl);
    cudaGetSymbolAddress((void**)&Wvh,  g_Wvh);
    cudaGetSymbolAddress((void**)&Woh,  g_Woh);
    cudaGetSymbolAddress((void**)&Xh,   g_Xh);
    cudaGetSymbolAddress((void**)&Xl,   g_Xl);
    cudaGetSymbolAddress((void**)&QKh,  g_QKh);
    cudaGetSymbolAddress((void**)&QKl,  g_QKl);
    cudaGetSymbolAddress((void**)&Vth,  g_Vth);
    cudaGetSymbolAddress((void**)&H,    g_H);

    cudaFuncSetAttribute(hgemm_qk, cudaFuncAttributeMaxDynamicSharedMemorySize,
                         QK_SMEM);
    cudaFuncSetAttribute(hgemm1, cudaFuncAttributeMaxDynamicSharedMemorySize,
                         G1_SMEM);
    cudaFuncSetAttribute(flash_attn, cudaFuncAttributeMaxDynamicSharedMemorySize,
                         FA_SMEM);

    // 1) fused weight prep + input conversion
    prep_w<<<dim3(2048, 6), 256>>>(Wqn, Wkn, Wqp, Wkp, Wvn, Wvp, Won, Wop,
                                   Wqkh, Wqkl, Wvh, Woh);
    cvt_pair<<<dim3(8192, 2), 256>>>(Xn, Xp, Xh, Xl);

    // 2) Q,K projections: fused 3-term, pair out, both streams
    hgemm_qk<<<dim3(8, 128, 2), 512, QK_SMEM>>>(Xh, Xl, Wqkh, Wqkl, QKh, QKl);

    // 3) V transposed, 1-term, mode 7 (remap, halfoff = 64*z), both streams
    hgemm1<<<dim3(128, 8, 2), 512, G1_SMEM>>>(
        Wvh, WSTR, 512, Xh, XSTR, 512, Vth, 0, ROWS, 512, 7, 64);

    // 4) fused flash attention, both softmax streams (z)
    flash_attn<<<dim3(8, 128, 2), 512, FA_SMEM>>>(
        QKh, QKl, Vth, H, H + QKSTR);

    // 5) output projections, 1-term, fp32 out, both streams (z)
    hgemm1<<<dim3(4, 128, 2), 512, G1_SMEM>>>(
        H, HSTR, 1024, Woh, WSTR, 1024, out, OSTR, 512, 1024, 1, 0);
}

// round 10
// speedup vs baseline: 1.0301x; 1.0301x over previous
#include <cuda_runtime.h>
#include <cuda_fp16.h>

// ===========================================================================
// B=16, N=1024, D=512, H=8, dk=64. ROWS=16384.
// HMMA (mma.sync m16n8k16), fp32 accum, split-fp16 where precision needs it:
//   QK proj: 3-term (Xh*Wh + Xl*Wh + Xh*Wl), pair out
//   S      : 2-term (Qh*Kh + Ql*Kh), online softmax in fused flash kernel
//   V proj : 1-term, out proj: 1-term, PV: V-hi only
// hgemm uses a 3-stage cp.async ring with a single barrier per K-chunk.
// ===========================================================================
#define ROWS 16384
#define PADK 72
#define TILEB (128 * PADK * 2)          // 18432 bytes per matrix tile
#define STAGEB (2 * TILEB)              // A+B per stage = 36864
#define GEMM_SMEM (3 * STAGEB)          // 110592

#define XSTR  ((long long)ROWS * 512)
#define WSTR  (524288LL)
#define QKSTR ((long long)ROWS * 1024)
#define HSTR  ((long long)ROWS * 1024)
#define OSTR  ((long long)ROWS * 512)

// Fused attention smem layout (bytes)
#define NKT   16
#define OFF_Q  0
#define OFF_KV 36864
#define KVBUF  27648
#define OFF_S  92160
#define OFF_P  125952
#define OFF_M  144384
#define OFF_L  144896
#define OFF_F  145408
#define FA_SMEM 145920

// ---------------------------------------------------------------------------
// Static device scratch
// ---------------------------------------------------------------------------
__device__ __half g_Wqkh[2][524288], g_Wqkl[2][524288];
__device__ __half g_Wvh [2][524288];
__device__ __half g_Woh [2][524288];
__device__ __half g_Xh  [2][8388608], g_Xl[2][8388608];
__device__ __half g_QKh [2][16777216], g_QKl[2][16777216];
__device__ __half g_Vth [2][16777216];
__device__ __half g_H   [2][16777216];

// ---------------------------------------------------------------------------
// PTX helpers
// ---------------------------------------------------------------------------
__device__ __forceinline__ unsigned smem_u32(const void* p) {
    unsigned a;
    asm("{ .reg .u64 t; cvta.to.shared.u64 t, %1; cvt.u32.u64 %0, t; }"
        : "=r"(a) : "l"(p));
    return a;
}
__device__ __forceinline__ void cpasync16(unsigned s, const void* g) {
    asm volatile("cp.async.cg.shared.global [%0], [%1], 16;" :: "r"(s), "l"(g));
}
__device__ __forceinline__ void cp_commit() {
    asm volatile("cp.async.commit_group;" ::: "memory");
}
__device__ __forceinline__ void cp_wait0() {
    asm volatile("cp.async.wait_group 0;" ::: "memory");
}
__device__ __forceinline__ void cp_wait1() {
    asm volatile("cp.async.wait_group 1;" ::: "memory");
}
__device__ __forceinline__ void ldm4(unsigned& r0, unsigned& r1, unsigned& r2,
                                     unsigned& r3, unsigned a) {
    asm volatile("ldmatrix.sync.aligned.m8n8.x4.shared.b16 {%0,%1,%2,%3}, [%4];"
                 : "=r"(r0), "=r"(r1), "=r"(r2), "=r"(r3) : "r"(a));
}
__device__ __forceinline__ void mma16816(float* c, const unsigned* a,
                                         const unsigned* b) {
    asm volatile(
        "mma.sync.aligned.m16n8k16.row.col.f32.f16.f16.f32 "
        "{%0,%1,%2,%3}, {%4,%5,%6,%7}, {%8,%9}, {%0,%1,%2,%3};"
        : "+f"(c[0]), "+f"(c[1]), "+f"(c[2]), "+f"(c[3])
        : "r"(a[0]), "r"(a[1]), "r"(a[2]), "r"(a[3]), "r"(b[0]), "r"(b[1]));
}
__device__ __forceinline__ void split2(float v0, float v1, __half2& hi, __half2& lo) {
    __half h0 = __float2half_rn(v0), h1 = __float2half_rn(v1);
    __half l0 = __float2half_rn(v0 - __half2float(h0));
    __half l1 = __float2half_rn(v1 - __half2float(h1));
    hi = __halves2half2(h0, h1);
    lo = __halves2half2(l0, l1);
}

// ---------------------------------------------------------------------------
// Multi-term HMMA GEMM: C = sum_t At(M,K)*Bt(N,K)^T, fp16 in, fp32 accum.
// 3-stage cp.async ring, ONE __syncthreads per K-chunk.
// blockIdx.z -> zb (stream) with per-operand strides sAb/sBb/sCb.
// modes: 1 fp32 out | 4 fp16 pair out | 7 fp16 single out + V row remap
//        (remap half offset = halfoff * zb).
// ---------------------------------------------------------------------------
__global__ __launch_bounds__(512)
void hgemm(const __half* __restrict__ A0, const __half* __restrict__ A1,
           const __half* __restrict__ A2,
           long long sAh, long long sAb, int lda,
           const __half* __restrict__ B0, const __half* __restrict__ B1,
           const __half* __restrict__ B2,
           long long sBh, long long sBb, int ldb,
           void* __restrict__ C0, void* __restrict__ C1,
           long long sCh, long long sCb, int ldc,
           int Kper, int nterm, int mode, int halfoff) {
    extern __shared__ __align__(16) char smem[];
    const unsigned sbase = smem_u32(smem);

    const int tid = threadIdx.x;
    const int wid = tid >> 5, lane = tid & 31;
    const int wm = wid & 3, wn = wid >> 2;

    const int zh = (int)(blockIdx.z >> 4), zb = (int)(blockIdx.z & 15);
    const long long aoff = sAh * zh + sAb * zb + (long long)(blockIdx.y * 128) * lda;
    const long long boff = sBh * zh + sBb * zb + (long long)(blockIdx.x * 128) * ldb;
    const __half* At[3] = {A0 + aoff, A1 ? A1 + aoff : A0, A2 ? A2 + aoff : A0};
    const __half* Bt[3] = {B0 + boff, B1 ? B1 + boff : B0, B2 ? B2 + boff : B0};

    const int r0c = tid >> 3, s0c = tid & 7;
    const int r1c = r0c + 64;
    const int trA0 = r0c * lda + s0c * 8, trA1 = r1c * lda + s0c * 8;
    const int trB0 = r0c * ldb + s0c * 8, trB1 = r1c * ldb + s0c * 8;
    const unsigned so0 = (unsigned)(r0c * PADK + s0c * 8) * 2;
    const unsigned so1 = (unsigned)(r1c * PADK + s0c * 8) * 2;

    const int T = Kper >> 6;
    const int TT = nterm * T;

#define LOAD_TILE(g, st)                                                      \
    do {                                                                      \
        int t_ = ((g) >= T) + ((g) >= 2 * T);                                 \
        int kk_ = (g) - t_ * T;                                               \
        const __half* ap = At[t_] + kk_ * 64;                                 \
        const __half* bp = Bt[t_] + kk_ * 64;                                 \
        unsigned sl = sbase + (st) * STAGEB;                                  \
        cpasync16(sl + so0, ap + trA0);                                       \
        cpasync16(sl + so1, ap + trA1);                                       \
        cpasync16(sl + TILEB + so0, bp + trB0);                               \
        cpasync16(sl + TILEB + so1, bp + trB1);                               \
        cp_commit();                                                          \
    } while (0)

    LOAD_TILE(0, 0);
    LOAD_TILE(1, 1);

    float acc[2][4][4];
#pragma unroll
    for (int i = 0; i < 2; i++)
#pragma unroll
        for (int j = 0; j < 4; j++)
#pragma unroll
            for (int k = 0; k < 4; k++) acc[i][j][k] = 0.f;

    const int sub = lane >> 3, r8 = lane & 7;

    int stage = 0, nstage = 2;   // stage of chunk g; stage for chunk g+2
    for (int g = 0; g < TT; g++) {
        if (g + 1 < TT) cp_wait1();
        else            cp_wait0();
        __syncthreads();
        if (g + 2 < TT) LOAD_TILE(g + 2, nstage);

        const unsigned ab = sbase + stage * STAGEB;
        const unsigned bb = ab + TILEB;
#pragma unroll
        for (int ks = 0; ks < 4; ks++) {
            const int k0 = ks * 16;
            unsigned a[2][4];
#pragma unroll
            for (int mi = 0; mi < 2; mi++) {
                int mrow = wm * 32 + mi * 16 + r8 + (sub & 1) * 8;
                int mcol = k0 + (sub >> 1) * 8;
                ldm4(a[mi][0], a[mi][1], a[mi][2], a[mi][3],
                     ab + (unsigned)(mrow * PADK + mcol) * 2);
            }
            unsigned b[4][2];
#pragma unroll
            for (int np = 0; np < 2; np++) {
                int nrow = wn * 32 + np * 16 + r8 + (sub >> 1) * 8;
                int kcol = k0 + (sub & 1) * 8;
                unsigned q0, q1, q2, q3;
                ldm4(q0, q1, q2, q3, bb + (unsigned)(nrow * PADK + kcol) * 2);
                b[np * 2][0] = q0; b[np * 2][1] = q1;
                b[np * 2 + 1][0] = q2; b[np * 2 + 1][1] = q3;
            }
#pragma unroll
            for (int mi = 0; mi < 2; mi++)
#pragma unroll
                for (int ni = 0; ni < 4; ni++)
                    mma16816(acc[mi][ni], a[mi], b[ni]);
        }
        stage = (stage + 1 == 3) ? 0 : stage + 1;
        nstage = (nstage + 1 == 3) ? 0 : nstage + 1;
    }
#undef LOAD_TILE

    const int trow = lane >> 2, tcol = (lane & 3) * 2;
    const long long coff = sCh * zh + sCb * zb;

#pragma unroll
    for (int mi = 0; mi < 2; mi++) {
#pragma unroll
        for (int ni = 0; ni < 4; ni++) {
            int rg = blockIdx.y * 128 + wm * 32 + mi * 16 + trow;
            int cg = blockIdx.x * 128 + wn * 32 + ni * 8 + tcol;
            float* ac = acc[mi][ni];
            if (mode == 1) {
                float* p0 = (float*)C0 + coff + (size_t)rg * ldc + cg;
                float* p1 = (float*)C0 + coff + (size_t)(rg + 8) * ldc + cg;
                *(float2*)p0 = make_float2(ac[0], ac[1]);
                *(float2*)p1 = make_float2(ac[2], ac[3]);
            } else if (mode == 4) {
                __half2 h, l;
                size_t o0 = coff + (size_t)rg * ldc + cg;
                size_t o1 = coff + (size_t)(rg + 8) * ldc + cg;
                split2(ac[0], ac[1], h, l);
                *(__half2*)((__half*)C0 + o0) = h;
                *(__half2*)((__half*)C1 + o0) = l;
                split2(ac[2], ac[3], h, l);
                *(__half2*)((__half*)C0 + o1) = h;
                *(__half2*)((__half*)C1 + o1) = l;
            } else {  // mode 7: single fp16 out + V row remap (halfoff * zb)
                int ho = halfoff * zb;
                int ra = ((rg >> 6) << 7) + (rg & 63) + ho;
                int rb0 = rg + 8;
                int rb = ((rb0 >> 6) << 7) + (rb0 & 63) + ho;
                *(__half2*)((__half*)C0 + (size_t)ra * ldc + cg) =
                    __floats2half2_rn(ac[0], ac[1]);
                *(__half2*)((__half*)C0 + (size_t)rb * ldc + cg) =
                    __floats2half2_rn(ac[2], ac[3]);
            }
        }
    }
}

// ---------------------------------------------------------------------------
// Fused flash attention, both softmax streams in one launch (blockIdx.z).
// S = Qh*Kh^T + Ql*Kh^T (Q pre-scaled 1/8), online softmax, O += P * Vh^T.
// ---------------------------------------------------------------------------
__global__ __launch_bounds__(512)
void flash_attn(const __half* __restrict__ QKhB, const __half* __restrict__ QKlB,
                const __half* __restrict__ VhB,
                __half* __restrict__ H0B, __half* __restrict__ H1B) {
    extern __shared__ __align__(16) char smem[];
    const unsigned sb = smem_u32(smem);
    float* Sf  = (float*)(smem + OFF_S);
    __half* Pm = (__half*)(smem + OFF_P);
    float* smM = (float*)(smem + OFF_M);
    float* smL = (float*)(smem + OFF_L);
    float* smF = (float*)(smem + OFF_F);

    const int tid = threadIdx.x, wid = tid >> 5, lane = tid & 31;
    const int wm = wid & 3, wn = wid >> 2;
    const int sub = lane >> 3, r8 = lane & 7;
    const int trow = lane >> 2, tcol = (lane & 3) * 2;
    const int qt = blockIdx.x, z = blockIdx.y;
    const int h = z >> 4, b = z & 15;
    const int s = blockIdx.z;

    const __half* QKh = QKhB + (size_t)s * QKSTR;
    const __half* QKl = QKlB + (size_t)s * QKSTR;
    const __half* Vh  = VhB  + (size_t)s * 16777216;
    __half* C0 = H0B + s * 64;
    __half* C1 = H1B + s * 64;

    if (tid < 128) { smM[tid] = -1e30f; smL[tid] = 0.f; }

    {
        const size_t rbase = (size_t)(b << 10) + qt * 128;
        int c0 = tid, c1 = tid + 512;
        int r0 = c0 >> 3, s0 = c0 & 7, r1 = c1 >> 3, s1 = c1 & 7;
        int col0 = h * 64 + s0 * 8, col1 = h * 64 + s1 * 8;
        cpasync16(sb + OFF_Q + (unsigned)(r0 * 72 + s0 * 8) * 2,
                  QKh + (rbase + r0) * 1024 + col0);
        cpasync16(sb + OFF_Q + (unsigned)(r1 * 72 + s1 * 8) * 2,
                  QKh + (rbase + r1) * 1024 + col1);
        cpasync16(sb + OFF_Q + 18432 + (unsigned)(r0 * 72 + s0 * 8) * 2,
                  QKl + (rbase + r0) * 1024 + col0);
        cpasync16(sb + OFF_Q + 18432 + (unsigned)(r1 * 72 + s1 * 8) * 2,
                  QKl + (rbase + r1) * 1024 + col1);
    }

#define LOAD_KV(kt, bi)                                                       \
    do {                                                                      \
        int rr = tid >> 3, ss = tid & 7;                                      \
        size_t gr = (size_t)(b << 10) + (kt) * 64 + rr;                       \
        unsigned sof = (unsigned)(rr * 72 + ss * 8) * 2;                      \
        cpasync16(sb + OFF_KV + (bi) * KVBUF + sof,                           \
                  QKh + gr * 1024 + 512 + h * 64 + ss * 8);                   \
        int v0 = tid, v1 = tid + 512;                                         \
        int vr0 = v0 >> 3, vs0 = v0 & 7, vr1 = v1 >> 3, vs1 = v1 & 7;         \
        size_t vcb = (size_t)(b << 10) + (kt) * 64;                           \
        cpasync16(sb + OFF_KV + (bi) * KVBUF + 9216 +                         \
                      (unsigned)(vr0 * 72 + vs0 * 8) * 2,                     \
                  Vh + (size_t)(h * 128 + vr0) * 16384 + vcb + vs0 * 8);      \
        cpasync16(sb + OFF_KV + (bi) * KVBUF + 9216 +                         \
                      (unsigned)(vr1 * 72 + vs1 * 8) * 2,                     \
                  Vh + (size_t)(h * 128 + vr1) * 16384 + vcb + vs1 * 8);      \
        cp_commit();                                                          \
    } while (0)

    LOAD_KV(0, 0);
    cp_wait0();

    float O[2][4][4] = {};

    for (int kt = 0; kt < NKT; kt++) {
        const int bi = kt & 1;
        if (kt) cp_wait0();
        __syncthreads();
        if (kt + 1 < NKT) LOAD_KV(kt + 1, bi ^ 1);

        const unsigned Kh = sb + OFF_KV + bi * KVBUF;
        const unsigned Vb = Kh + 9216;

        float acc[2][2][4] = {};
#pragma unroll
        for (int ks = 0; ks < 4; ks++) {
            const int k0 = ks * 16;
            unsigned ah[2][4], al[2][4];
#pragma unroll
            for (int mi = 0; mi < 2; mi++) {
                unsigned off = (unsigned)((wm * 32 + mi * 16 + r8 + (sub & 1) * 8) * 72 +
                                          k0 + (sub >> 1) * 8) * 2;
                ldm4(ah[mi][0], ah[mi][1], ah[mi][2], ah[mi][3], sb + OFF_Q + off);
                ldm4(al[mi][0], al[mi][1], al[mi][2], al[mi][3],
                     sb + OFF_Q + 18432 + off);
            }
            unsigned bh[2][2];
            {
                unsigned off = (unsigned)((wn * 16 + r8 + (sub >> 1) * 8) * 72 +
                                          k0 + (sub & 1) * 8) * 2;
                unsigned q0, q1, q2, q3;
                ldm4(q0, q1, q2, q3, Kh + off);
                bh[0][0] = q0; bh[0][1] = q1; bh[1][0] = q2; bh[1][1] = q3;
            }
#pragma unroll
            for (int mi = 0; mi < 2; mi++)
#pragma unroll
                for (int nf = 0; nf < 2; nf++) {
                    mma16816(acc[mi][nf], ah[mi], bh[nf]);
                    mma16816(acc[mi][nf], al[mi], bh[nf]);
                }
        }
#pragma unroll
        for (int mi = 0; mi < 2; mi++)
#pragma unroll
            for (int nf = 0; nf < 2; nf++) {
                int r0 = wm * 32 + mi * 16 + trow;
                int col = wn * 16 + nf * 8 + tcol;
                *(float2*)&Sf[r0 * 66 + col] =
                    make_float2(acc[mi][nf][0], acc[mi][nf][1]);
                *(float2*)&Sf[(r0 + 8) * 66 + col] =
                    make_float2(acc[mi][nf][2], acc[mi][nf][3]);
            }
        __syncthreads();

        {
            int r = tid >> 2, seg = tid & 3;
            float vals[16];
            float* bp = &Sf[r * 66 + seg * 16];
#pragma unroll
            for (int i = 0; i < 8; i++) {
                float2 t2 = *(float2*)(bp + 2 * i);
                vals[2 * i] = t2.x; vals[2 * i + 1] = t2.y;
            }
            float mt = vals[0];
#pragma unroll
            for (int i = 1; i < 16; i++) mt = fmaxf(mt, vals[i]);
            mt = fmaxf(mt, __shfl_xor_sync(~0u, mt, 1));
            mt = fmaxf(mt, __shfl_xor_sync(~0u, mt, 2));
            float mo = smM[r];
            float mn = fmaxf(mo, mt);
            float f = __expf(mo - mn);
            float sum = 0.f;
            __half* pp = &Pm[r * 72 + seg * 16];
#pragma unroll
            for (int i = 0; i < 8; i++) {
                float e0 = __expf(vals[2 * i] - mn);
                float e1 = __expf(vals[2 * i + 1] - mn);
                *(__half2*)(pp + 2 * i) = __floats2half2_rn(e0, e1);
                sum += e0 + e1;
            }
            sum += __shfl_xor_sync(~0u, sum, 1);
            sum += __shfl_xor_sync(~0u, sum, 2);
            if (seg == 0) {
                smM[r] = mn;
                smL[r] = smL[r] * f + sum;
                smF[r] = f;
            }
        }
        __syncthreads();

#pragma unroll
        for (int mi = 0; mi < 2; mi++) {
            float f0 = smF[wm * 32 + mi * 16 + trow];
            float f1 = smF[wm * 32 + mi * 16 + trow + 8];
#pragma unroll
            for (int nf = 0; nf < 4; nf++) {
                O[mi][nf][0] *= f0; O[mi][nf][1] *= f0;
                O[mi][nf][2] *= f1; O[mi][nf][3] *= f1;
            }
        }
#pragma unroll
        for (int ks = 0; ks < 4; ks++) {
            const int k0 = ks * 16;
            unsigned aP[2][4];
#pragma unroll
            for (int mi = 0; mi < 2; mi++) {
                unsigned off = (unsigned)((wm * 32 + mi * 16 + r8 + (sub & 1) * 8) * 72 +
                                          k0 + (sub >> 1) * 8) * 2;
                ldm4(aP[mi][0], aP[mi][1], aP[mi][2], aP[mi][3], sb + OFF_P + off);
            }
            unsigned bV[4][2];
#pragma unroll
            for (int np = 0; np < 2; np++) {
                unsigned off = (unsigned)((wn * 32 + np * 16 + r8 + (sub >> 1) * 8) * 72 +
                                          k0 + (sub & 1) * 8) * 2;
                unsigned q0, q1, q2, q3;
                ldm4(q0, q1, q2, q3, Vb + off);
                bV[np * 2][0] = q0; bV[np * 2][1] = q1;
                bV[np * 2 + 1][0] = q2; bV[np * 2 + 1][1] = q3;
            }
#pragma unroll
            for (int mi = 0; mi < 2; mi++)
#pragma unroll
                for (int nf = 0; nf < 4; nf++)
                    mma16816(O[mi][nf], aP[mi], bV[nf]);
        }
    }
#undef LOAD_KV

    const long long coff = 128LL * h + 1048576LL * b;
#pragma unroll
    for (int mi = 0; mi < 2; mi++) {
        int r0 = wm * 32 + mi * 16 + trow;
        float inv0 = 1.f / smL[r0], inv1 = 1.f / smL[r0 + 8];
        int rg0 = qt * 128 + r0, rg1 = rg0 + 8;
#pragma unroll
        for (int nf = 0; nf < 4; nf++) {
            int cg = wn * 32 + nf * 8 + tcol;
            __half* base = (cg < 64) ? C0 : C1;
            int cl = cg & 63;
            *(__half2*)(base + coff + (size_t)rg0 * 1024 + cl) =
                __floats2half2_rn(O[mi][nf][0] * inv0, O[mi][nf][1] * inv0);
            *(__half2*)(base + coff + (size_t)rg1 * 1024 + cl) =
                __floats2half2_rn(O[mi][nf][2] * inv1, O[mi][nf][3] * inv1);
        }
    }
}

// ---------------------------------------------------------------------------
// Fused weight prep: blockIdx.y = task (0/1 qk n/p, 2/3 v n/p, 4/5 wo n/p)
// ---------------------------------------------------------------------------
__global__ void prep_w(const float* __restrict__ Wqn, const float* __restrict__ Wkn,
                       const float* __restrict__ Wqp, const float* __restrict__ Wkp,
                       const float* __restrict__ Wvn, const float* __restrict__ Wvp,
                       const float* __restrict__ Won, const float* __restrict__ Wop,
                       __half* __restrict__ Wqkh, __half* __restrict__ Wqkl,
                       __half* __restrict__ Wvh, __half* __restrict__ Woh) {
    int idx = blockIdx.x * blockDim.x + threadIdx.x;
    if (idx >= 524288) return;
    int task = blockIdx.y;
    int st = task & 1;
    if (task < 2) {
        const float* Wq = st ? Wqp : Wqn;
        const float* Wk = st ? Wkp : Wkn;
        int j = idx >> 9, d = idx & 511;
        int jj = j & 511;
        float v;
        if (j < 512)
            v = Wq[((size_t)((jj >> 6) * 512 + d)) * 64 + (jj & 63)] * 0.125f;
        else
            v = Wk[((size_t)((jj >> 6) * 512 + d)) * 64 + (jj & 63)];
        __half h = __float2half_rn(v);
        Wqkh[(size_t)st * WSTR + idx] = h;
        Wqkl[(size_t)st * WSTR + idx] = __float2half_rn(v - __half2float(h));
    } else if (task < 4) {
        const float* Wv = st ? Wvp : Wvn;
        int j = idx >> 9, d = idx & 511;
        Wvh[(size_t)st * WSTR + idx] =
            __float2half_rn(Wv[((size_t)((j >> 6) * 512 + d)) * 64 + (j & 63)]);
    } else {
        const float* Wo = st ? Wop : Won;
        int e = idx >> 10, j = idx & 1023;
        Woh[(size_t)st * WSTR + idx] = __float2half_rn(Wo[(size_t)j * 512 + e]);
    }
}

__global__ void cvt_pair(const float* __restrict__ Xn, const float* __restrict__ Xp,
                         __half* __restrict__ Yh, __half* __restrict__ Yl) {
    int i = blockIdx.x * blockDim.x + threadIdx.x;
    if (i >= ROWS * 512 / 4) return;
    int st = blockIdx.y;
    const float* X = st ? Xp : Xn;
    float4 v = ((const float4*)X)[i];
    __half2 h0, l0, h1, l1;
    split2(v.x, v.y, h0, l0);
    split2(v.z, v.w, h1, l1);
    uint2 uh, ul;
    uh.x = *reinterpret_cast<unsigned*>(&h0);
    uh.y = *reinterpret_cast<unsigned*>(&h1);
    ul.x = *reinterpret_cast<unsigned*>(&l0);
    ul.y = *reinterpret_cast<unsigned*>(&l1);
    ((uint2*)(Yh + (size_t)st * XSTR))[i] = uh;
    ((uint2*)(Yl + (size_t)st * XSTR))[i] = ul;
}

// ---------------------------------------------------------------------------
// Host launcher: 6 kernel launches
// ---------------------------------------------------------------------------
extern "C" void kernel_launch(void* const* d_in, const int* in_sizes, int n_in,
                              void* d_out, int out_size) {
    const float* Xn  = (const float*)d_in[0];
    const float* Xp  = (const float*)d_in[1];
    const float* Wqn = (const float*)d_in[2];
    const float* Wqp = (const float*)d_in[3];
    const float* Wkn = (const float*)d_in[4];
    const float* Wkp = (const float*)d_in[5];
    const float* Wvn = (const float*)d_in[6];
    const float* Wvp = (const float*)d_in[7];
    const float* Won = (const float*)d_in[8];
    const float* Wop = (const float*)d_in[9];
    float* out = (float*)d_out;

    __half *Wqkh, *Wqkl, *Wvh, *Woh, *Xh, *Xl, *QKh, *QKl, *Vth, *H;
    cudaGetSymbolAddress((void**)&Wqkh, g_Wqkh);
    cudaGetSymbolAddress((void**)&Wqkl, g_Wqkl);
    cudaGetSymbolAddress((void**)&Wvh,  g_Wvh);
    cudaGetSymbolAddress((void**)&Woh,  g_Woh);
    cudaGetSymbolAddress((void**)&Xh,   g_Xh);
    cudaGetSymbolAddress((void**)&Xl,   g_Xl);
    cudaGetSymbolAddress((void**)&QKh,  g_QKh);
    cudaGetSymbolAddress((void**)&QKl,  g_QKl);
    cudaGetSymbolAddress((void**)&Vth,  g_Vth);
    cudaGetSymbolAddress((void**)&H,    g_H);

    cudaFuncSetAttribute(hgemm, cudaFuncAttributeMaxDynamicSharedMemorySize,
                         GEMM_SMEM);
    cudaFuncSetAttribute(flash_attn, cudaFuncAttributeMaxDynamicSharedMemorySize,
                         FA_SMEM);

    // 1) fused weight prep + input conversion
    prep_w<<<dim3(2048, 6), 256>>>(Wqn, Wkn, Wqp, Wkp, Wvn, Wvp, Won, Wop,
                                   Wqkh, Wqkl, Wvh, Woh);
    cvt_pair<<<dim3(8192, 2), 256>>>(Xn, Xp, Xh, Xl);

    // 2) Q,K projections, 3-term, pair out, both streams (z)
    hgemm<<<dim3(8, 128, 2), 512, GEMM_SMEM>>>(
        Xh, Xl, Xh, 0, XSTR, 512,
        Wqkh, Wqkh, Wqkl, 0, WSTR, 512,
        QKh, QKl, 0, QKSTR, 1024, 512, 3, 4, 0);

    // 3) V transposed, 1-term, mode 7 (remap, halfoff = 64*z), both streams
    hgemm<<<dim3(128, 8, 2), 512, GEMM_SMEM>>>(
        Wvh, nullptr, nullptr, 0, WSTR, 512,
        Xh, nullptr, nullptr, 0, XSTR, 512,
        Vth, nullptr, 0, 0, ROWS, 512, 1, 7, 64);

    // 4) fused flash attention, both softmax streams (z)
    flash_attn<<<dim3(8, 128, 2), 512, FA_SMEM>>>(
        QKh, QKl, Vth, H, H + QKSTR);

    // 5) output projections, 1-term, fp32 out, both streams (z)
    hgemm<<<dim3(4, 128, 2), 512, GEMM_SMEM>>>(
        H, nullptr, nullptr, 0, HSTR, 1024,
        Woh, nullptr, nullptr, 0, WSTR, 1024,
        out, nullptr, 0, OSTR, 512, 1024, 1, 1, 0);
}

// round 11
// speedup vs baseline: 1.0564x; 1.0255x over previous
#include <cuda_runtime.h>
#include <cuda_fp16.h>

// ===========================================================================
// B=16, N=1024, D=512, H=8, dk=64. ROWS=16384.
// HMMA (mma.sync m16n8k16), fp32 accum, split-fp16 where precision needs it:
//   QK proj: 3-term (Xh*Wh + Xl*Wh + Xh*Wl), pair out
//   S      : 2-term (Qh*Kh + Ql*Kh), online softmax in fused flash kernel
//   V proj : 1-term, out proj: 1-term, PV: V-hi only
// hgemm: 256 threads, 64x32 warp tiles (crossbar-traffic reduction).
// ===========================================================================
#define ROWS 16384
#define PADK 72
#define TILEB (128 * PADK * 2)
#define GEMM_SMEM (4 * TILEB)           // 2 stages x (A+B) = 73728

#define XSTR  ((long long)ROWS * 512)
#define WSTR  (524288LL)
#define QKSTR ((long long)ROWS * 1024)
#define HSTR  ((long long)ROWS * 1024)
#define OSTR  ((long long)ROWS * 512)

// Fused attention smem layout (bytes)
#define NKT   16
#define OFF_Q  0
#define OFF_KV 36864
#define KVBUF  27648
#define OFF_S  92160
#define OFF_P  125952
#define OFF_M  144384
#define OFF_L  144896
#define OFF_F  145408
#define FA_SMEM 145920

// ---------------------------------------------------------------------------
// Static device scratch
// ---------------------------------------------------------------------------
__device__ __half g_Wqkh[2][524288], g_Wqkl[2][524288];
__device__ __half g_Wvh [2][524288];
__device__ __half g_Woh [2][524288];
__device__ __half g_Xh  [2][8388608], g_Xl[2][8388608];
__device__ __half g_QKh [2][16777216], g_QKl[2][16777216];
__device__ __half g_Vth [2][16777216];
__device__ __half g_H   [2][16777216];

// ---------------------------------------------------------------------------
// PTX helpers
// ---------------------------------------------------------------------------
__device__ __forceinline__ unsigned smem_u32(const void* p) {
    unsigned a;
    asm("{ .reg .u64 t; cvta.to.shared.u64 t, %1; cvt.u32.u64 %0, t; }"
        : "=r"(a) : "l"(p));
    return a;
}
__device__ __forceinline__ void cpasync16(unsigned s, const void* g) {
    asm volatile("cp.async.cg.shared.global [%0], [%1], 16;" :: "r"(s), "l"(g));
}
__device__ __forceinline__ void cp_commit() {
    asm volatile("cp.async.commit_group;" ::: "memory");
}
__device__ __forceinline__ void cp_wait0() {
    asm volatile("cp.async.wait_group 0;" ::: "memory");
}
__device__ __forceinline__ void ldm4(unsigned& r0, unsigned& r1, unsigned& r2,
                                     unsigned& r3, unsigned a) {
    asm volatile("ldmatrix.sync.aligned.m8n8.x4.shared.b16 {%0,%1,%2,%3}, [%4];"
                 : "=r"(r0), "=r"(r1), "=r"(r2), "=r"(r3) : "r"(a));
}
__device__ __forceinline__ void mma16816(float* c, const unsigned* a,
                                         const unsigned* b) {
    asm volatile(
        "mma.sync.aligned.m16n8k16.row.col.f32.f16.f16.f32 "
        "{%0,%1,%2,%3}, {%4,%5,%6,%7}, {%8,%9}, {%0,%1,%2,%3};"
        : "+f"(c[0]), "+f"(c[1]), "+f"(c[2]), "+f"(c[3])
        : "r"(a[0]), "r"(a[1]), "r"(a[2]), "r"(a[3]), "r"(b[0]), "r"(b[1]));
}
__device__ __forceinline__ void split2(float v0, float v1, __half2& hi, __half2& lo) {
    __half h0 = __float2half_rn(v0), h1 = __float2half_rn(v1);
    __half l0 = __float2half_rn(v0 - __half2float(h0));
    __half l1 = __float2half_rn(v1 - __half2float(h1));
    hi = __halves2half2(h0, h1);
    lo = __halves2half2(l0, l1);
}

// ---------------------------------------------------------------------------
// Multi-term HMMA GEMM: C = sum_t At(M,K)*Bt(N,K)^T, fp16 in, fp32 accum.
// 256 threads, 8 warps, warp tile 64(M) x 32(N): 6 LDSM -> 16 MMA per ks.
// Two-stage cp.async double buffer (R8-proven structure).
// blockIdx.z -> zb (stream). modes: 1 fp32 | 4 fp16 pair | 7 fp16 + V remap.
// ---------------------------------------------------------------------------
__global__ __launch_bounds__(256, 2)
void hgemm(const __half* __restrict__ A0, const __half* __restrict__ A1,
           const __half* __restrict__ A2,
           long long sAh, long long sAb, int lda,
           const __half* __restrict__ B0, const __half* __restrict__ B1,
           const __half* __restrict__ B2,
           long long sBh, long long sBb, int ldb,
           void* __restrict__ C0, void* __restrict__ C1,
           long long sCh, long long sCb, int ldc,
           int Kper, int nterm, int mode, int halfoff) {
    extern __shared__ __align__(16) char smem[];
    const unsigned smA = smem_u32(smem);
    const unsigned smB = smA + 2 * TILEB;

    const int tid = threadIdx.x;
    const int wid = tid >> 5, lane = tid & 31;
    const int wm = wid & 1, wn = wid >> 1;       // 2 x 4 warps

    const int zh = (int)(blockIdx.z >> 4), zb = (int)(blockIdx.z & 15);
    const long long aoff = sAh * zh + sAb * zb + (long long)(blockIdx.y * 128) * lda;
    const long long boff = sBh * zh + sBb * zb + (long long)(blockIdx.x * 128) * ldb;
    const __half* At[3] = {A0 + aoff, A1 ? A1 + aoff : A0, A2 ? A2 + aoff : A0};
    const __half* Bt[3] = {B0 + boff, B1 ? B1 + boff : B0, B2 ? B2 + boff : B0};

    // loader: 1024 16B chunks per matrix, 4 per thread (256 threads)
    int trA[4], trB[4];
    unsigned so[4];
#pragma unroll
    for (int i = 0; i < 4; i++) {
        int c = tid + i * 256;
        int r = c >> 3, s = c & 7;
        trA[i] = r * lda + s * 8;
        trB[i] = r * ldb + s * 8;
        so[i] = (unsigned)(r * PADK + s * 8) * 2;
    }

    const int T = Kper >> 6;
    const int TT = nterm * T;

#define LOAD_TILE(g, bf)                                                      \
    do {                                                                      \
        int t_ = ((g) >= T) + ((g) >= 2 * T);                                 \
        int kk_ = (g) - t_ * T;                                               \
        const __half* ap = At[t_] + kk_ * 64;                                 \
        const __half* bp = Bt[t_] + kk_ * 64;                                 \
        unsigned sa = smA + (bf) * TILEB;                                     \
        unsigned sbm = smB + (bf) * TILEB;                                    \
        _Pragma("unroll")                                                     \
        for (int i_ = 0; i_ < 4; i_++) {                                      \
            cpasync16(sa + so[i_], ap + trA[i_]);                             \
            cpasync16(sbm + so[i_], bp + trB[i_]);                            \
        }                                                                     \
        cp_commit();                                                          \
    } while (0)

    LOAD_TILE(0, 0);

    float acc[4][4][4];
#pragma unroll
    for (int i = 0; i < 4; i++)
#pragma unroll
        for (int j = 0; j < 4; j++)
#pragma unroll
            for (int k = 0; k < 4; k++) acc[i][j][k] = 0.f;

    const int sub = lane >> 3, r8 = lane & 7;

    for (int g = 0; g < TT; g++) {
        const int bf = g & 1;
        cp_wait0();
        __syncthreads();
        if (g + 1 < TT) LOAD_TILE(g + 1, bf ^ 1);

        const unsigned ab = smA + bf * TILEB;
        const unsigned bb = smB + bf * TILEB;
#pragma unroll
        for (int ks = 0; ks < 4; ks++) {
            const int k0 = ks * 16;
            unsigned a[4][4];
#pragma unroll
            for (int mi = 0; mi < 4; mi++) {
                int mrow = wm * 64 + mi * 16 + r8 + (sub & 1) * 8;
                int mcol = k0 + (sub >> 1) * 8;
                ldm4(a[mi][0], a[mi][1], a[mi][2], a[mi][3],
                     ab + (unsigned)(mrow * PADK + mcol) * 2);
            }
            unsigned b[4][2];
#pragma unroll
            for (int np = 0; np < 2; np++) {
                int nrow = wn * 32 + np * 16 + r8 + (sub >> 1) * 8;
                int kcol = k0 + (sub & 1) * 8;
                unsigned q0, q1, q2, q3;
                ldm4(q0, q1, q2, q3, bb + (unsigned)(nrow * PADK + kcol) * 2);
                b[np * 2][0] = q0; b[np * 2][1] = q1;
                b[np * 2 + 1][0] = q2; b[np * 2 + 1][1] = q3;
            }
#pragma unroll
            for (int mi = 0; mi < 4; mi++)
#pragma unroll
                for (int ni = 0; ni < 4; ni++)
                    mma16816(acc[mi][ni], a[mi], b[ni]);
        }
        __syncthreads();
    }
#undef LOAD_TILE

    const int trow = lane >> 2, tcol = (lane & 3) * 2;
    const long long coff = sCh * zh + sCb * zb;

#pragma unroll
    for (int mi = 0; mi < 4; mi++) {
#pragma unroll
        for (int ni = 0; ni < 4; ni++) {
            int rg = blockIdx.y * 128 + wm * 64 + mi * 16 + trow;
            int cg = blockIdx.x * 128 + wn * 32 + ni * 8 + tcol;
            float* ac = acc[mi][ni];
            if (mode == 1) {
                float* p0 = (float*)C0 + coff + (size_t)rg * ldc + cg;
                float* p1 = (float*)C0 + coff + (size_t)(rg + 8) * ldc + cg;
                *(float2*)p0 = make_float2(ac[0], ac[1]);
                *(float2*)p1 = make_float2(ac[2], ac[3]);
            } else if (mode == 4) {
                __half2 h, l;
                size_t o0 = coff + (size_t)rg * ldc + cg;
                size_t o1 = coff + (size_t)(rg + 8) * ldc + cg;
                split2(ac[0], ac[1], h, l);
                *(__half2*)((__half*)C0 + o0) = h;
                *(__half2*)((__half*)C1 + o0) = l;
                split2(ac[2], ac[3], h, l);
                *(__half2*)((__half*)C0 + o1) = h;
                *(__half2*)((__half*)C1 + o1) = l;
            } else {  // mode 7: single fp16 out + V row remap (halfoff * zb)
                int ho = halfoff * zb;
                int ra = ((rg >> 6) << 7) + (rg & 63) + ho;
                int rb0 = rg + 8;
                int rb = ((rb0 >> 6) << 7) + (rb0 & 63) + ho;
                *(__half2*)((__half*)C0 + (size_t)ra * ldc + cg) =
                    __floats2half2_rn(ac[0], ac[1]);
                *(__half2*)((__half*)C0 + (size_t)rb * ldc + cg) =
                    __floats2half2_rn(ac[2], ac[3]);
            }
        }
    }
}

// ---------------------------------------------------------------------------
// Fused flash attention (unchanged from R8), both streams via blockIdx.z.
// ---------------------------------------------------------------------------
__global__ __launch_bounds__(512)
void flash_attn(const __half* __restrict__ QKhB, const __half* __restrict__ QKlB,
                const __half* __restrict__ VhB,
                __half* __restrict__ H0B, __half* __restrict__ H1B) {
    extern __shared__ __align__(16) char smem[];
    const unsigned sb = smem_u32(smem);
    float* Sf  = (float*)(smem + OFF_S);
    __half* Pm = (__half*)(smem + OFF_P);
    float* smM = (float*)(smem + OFF_M);
    float* smL = (float*)(smem + OFF_L);
    float* smF = (float*)(smem + OFF_F);

    const int tid = threadIdx.x, wid = tid >> 5, lane = tid & 31;
    const int wm = wid & 3, wn = wid >> 2;
    const int sub = lane >> 3, r8 = lane & 7;
    const int trow = lane >> 2, tcol = (lane & 3) * 2;
    const int qt = blockIdx.x, z = blockIdx.y;
    const int h = z >> 4, b = z & 15;
    const int s = blockIdx.z;

    const __half* QKh = QKhB + (size_t)s * QKSTR;
    const __half* QKl = QKlB + (size_t)s * QKSTR;
    const __half* Vh  = VhB  + (size_t)s * 16777216;
    __half* C0 = H0B + s * 64;
    __half* C1 = H1B + s * 64;

    if (tid < 128) { smM[tid] = -1e30f; smL[tid] = 0.f; }

    {
        const size_t rbase = (size_t)(b << 10) + qt * 128;
        int c0 = tid, c1 = tid + 512;
        int r0 = c0 >> 3, s0 = c0 & 7, r1 = c1 >> 3, s1 = c1 & 7;
        int col0 = h * 64 + s0 * 8, col1 = h * 64 + s1 * 8;
        cpasync16(sb + OFF_Q + (unsigned)(r0 * 72 + s0 * 8) * 2,
                  QKh + (rbase + r0) * 1024 + col0);
        cpasync16(sb + OFF_Q + (unsigned)(r1 * 72 + s1 * 8) * 2,
                  QKh + (rbase + r1) * 1024 + col1);
        cpasync16(sb + OFF_Q + 18432 + (unsigned)(r0 * 72 + s0 * 8) * 2,
                  QKl + (rbase + r0) * 1024 + col0);
        cpasync16(sb + OFF_Q + 18432 + (unsigned)(r1 * 72 + s1 * 8) * 2,
                  QKl + (rbase + r1) * 1024 + col1);
    }

#define LOAD_KV(kt, bi)                                                       \
    do {                                                                      \
        int rr = tid >> 3, ss = tid & 7;                                      \
        size_t gr = (size_t)(b << 10) + (kt) * 64 + rr;                       \
        unsigned sof = (unsigned)(rr * 72 + ss * 8) * 2;                      \
        cpasync16(sb + OFF_KV + (bi) * KVBUF + sof,                           \
                  QKh + gr * 1024 + 512 + h * 64 + ss * 8);                   \
        int v0 = tid, v1 = tid + 512;                                         \
        int vr0 = v0 >> 3, vs0 = v0 & 7, vr1 = v1 >> 3, vs1 = v1 & 7;         \
        size_t vcb = (size_t)(b << 10) + (kt) * 64;                           \
        cpasync16(sb + OFF_KV + (bi) * KVBUF + 9216 +                         \
                      (unsigned)(vr0 * 72 + vs0 * 8) * 2,                     \
                  Vh + (size_t)(h * 128 + vr0) * 16384 + vcb + vs0 * 8);      \
        cpasync16(sb + OFF_KV + (bi) * KVBUF + 9216 +                         \
                      (unsigned)(vr1 * 72 + vs1 * 8) * 2,                     \
                  Vh + (size_t)(h * 128 + vr1) * 16384 + vcb + vs1 * 8);      \
        cp_commit();                                                          \
    } while (0)

    LOAD_KV(0, 0);
    cp_wait0();

    float O[2][4][4] = {};

    for (int kt = 0; kt < NKT; kt++) {
        const int bi = kt & 1;
        if (kt) cp_wait0();
        __syncthreads();
        if (kt + 1 < NKT) LOAD_KV(kt + 1, bi ^ 1);

        const unsigned Kh = sb + OFF_KV + bi * KVBUF;
        const unsigned Vb = Kh + 9216;

        float acc[2][2][4] = {};
#pragma unroll
        for (int ks = 0; ks < 4; ks++) {
            const int k0 = ks * 16;
            unsigned ah[2][4], al[2][4];
#pragma unroll
            for (int mi = 0; mi < 2; mi++) {
                unsigned off = (unsigned)((wm * 32 + mi * 16 + r8 + (sub & 1) * 8) * 72 +
                                          k0 + (sub >> 1) * 8) * 2;
                ldm4(ah[mi][0], ah[mi][1], ah[mi][2], ah[mi][3], sb + OFF_Q + off);
                ldm4(al[mi][0], al[mi][1], al[mi][2], al[mi][3],
                     sb + OFF_Q + 18432 + off);
            }
            unsigned bh[2][2];
            {
                unsigned off = (unsigned)((wn * 16 + r8 + (sub >> 1) * 8) * 72 +
                                          k0 + (sub & 1) * 8) * 2;
                unsigned q0, q1, q2, q3;
                ldm4(q0, q1, q2, q3, Kh + off);
                bh[0][0] = q0; bh[0][1] = q1; bh[1][0] = q2; bh[1][1] = q3;
            }
#pragma unroll
            for (int mi = 0; mi < 2; mi++)
#pragma unroll
                for (int nf = 0; nf < 2; nf++) {
                    mma16816(acc[mi][nf], ah[mi], bh[nf]);
                    mma16816(acc[mi][nf], al[mi], bh[nf]);
                }
        }
#pragma unroll
        for (int mi = 0; mi < 2; mi++)
#pragma unroll
            for (int nf = 0; nf < 2; nf++) {
                int r0 = wm * 32 + mi * 16 + trow;
                int col = wn * 16 + nf * 8 + tcol;
                *(float2*)&Sf[r0 * 66 + col] =
                    make_float2(acc[mi][nf][0], acc[mi][nf][1]);
                *(float2*)&Sf[(r0 + 8) * 66 + col] =
                    make_float2(acc[mi][nf][2], acc[mi][nf][3]);
            }
        __syncthreads();

        {
            int r = tid >> 2, seg = tid & 3;
            float vals[16];
            float* bp = &Sf[r * 66 + seg * 16];
#pragma unroll
            for (int i = 0; i < 8; i++) {
                float2 t2 = *(float2*)(bp + 2 * i);
                vals[2 * i] = t2.x; vals[2 * i + 1] = t2.y;
            }
            float mt = vals[0];
#pragma unroll
            for (int i = 1; i < 16; i++) mt = fmaxf(mt, vals[i]);
            mt = fmaxf(mt, __shfl_xor_sync(~0u, mt, 1));
            mt = fmaxf(mt, __shfl_xor_sync(~0u, mt, 2));
            float mo = smM[r];
            float mn = fmaxf(mo, mt);
            float f = __expf(mo - mn);
            float sum = 0.f;
            __half* pp = &Pm[r * 72 + seg * 16];
#pragma unroll
            for (int i = 0; i < 8; i++) {
                float e0 = __expf(vals[2 * i] - mn);
                float e1 = __expf(vals[2 * i + 1] - mn);
                *(__half2*)(pp + 2 * i) = __floats2half2_rn(e0, e1);
                sum += e0 + e1;
            }
            sum += __shfl_xor_sync(~0u, sum, 1);
            sum += __shfl_xor_sync(~0u, sum, 2);
            if (seg == 0) {
                smM[r] = mn;
                smL[r] = smL[r] * f + sum;
                smF[r] = f;
            }
        }
        __syncthreads();

#pragma unroll
        for (int mi = 0; mi < 2; mi++) {
            float f0 = smF[wm * 32 + mi * 16 + trow];
            float f1 = smF[wm * 32 + mi * 16 + trow + 8];
#pragma unroll
            for (int nf = 0; nf < 4; nf++) {
                O[mi][nf][0] *= f0; O[mi][nf][1] *= f0;
                O[mi][nf][2] *= f1; O[mi][nf][3] *= f1;
            }
        }
#pragma unroll
        for (int ks = 0; ks < 4; ks++) {
            const int k0 = ks * 16;
            unsigned aP[2][4];
#pragma unroll
            for (int mi = 0; mi < 2; mi++) {
                unsigned off = (unsigned)((wm * 32 + mi * 16 + r8 + (sub & 1) * 8) * 72 +
                                          k0 + (sub >> 1) * 8) * 2;
                ldm4(aP[mi][0], aP[mi][1], aP[mi][2], aP[mi][3], sb + OFF_P + off);
            }
            unsigned bV[4][2];
#pragma unroll
            for (int np = 0; np < 2; np++) {
                unsigned off = (unsigned)((wn * 32 + np * 16 + r8 + (sub >> 1) * 8) * 72 +
                                          k0 + (sub & 1) * 8) * 2;
                unsigned q0, q1, q2, q3;
                ldm4(q0, q1, q2, q3, Vb + off);
                bV[np * 2][0] = q0; bV[np * 2][1] = q1;
                bV[np * 2 + 1][0] = q2; bV[np * 2 + 1][1] = q3;
            }
#pragma unroll
            for (int mi = 0; mi < 2; mi++)
#pragma unroll
                for (int nf = 0; nf < 4; nf++)
                    mma16816(O[mi][nf], aP[mi], bV[nf]);
        }
    }
#undef LOAD_KV

    const long long coff = 128LL * h + 1048576LL * b;
#pragma unroll
    for (int mi = 0; mi < 2; mi++) {
        int r0 = wm * 32 + mi * 16 + trow;
        float inv0 = 1.f / smL[r0], inv1 = 1.f / smL[r0 + 8];
        int rg0 = qt * 128 + r0, rg1 = rg0 + 8;
#pragma unroll
        for (int nf = 0; nf < 4; nf++) {
            int cg = wn * 32 + nf * 8 + tcol;
            __half* base = (cg < 64) ? C0 : C1;
            int cl = cg & 63;
            *(__half2*)(base + coff + (size_t)rg0 * 1024 + cl) =
                __floats2half2_rn(O[mi][nf][0] * inv0, O[mi][nf][1] * inv0);
            *(__half2*)(base + coff + (size_t)rg1 * 1024 + cl) =
                __floats2half2_rn(O[mi][nf][2] * inv1, O[mi][nf][3] * inv1);
        }
    }
}

// ---------------------------------------------------------------------------
// Fused weight prep + input conversion (unchanged)
// ---------------------------------------------------------------------------
__global__ void prep_w(const float* __restrict__ Wqn, const float* __restrict__ Wkn,
                       const float* __restrict__ Wqp, const float* __restrict__ Wkp,
                       const float* __restrict__ Wvn, const float* __restrict__ Wvp,
                       const float* __restrict__ Won, const float* __restrict__ Wop,
                       __half* __restrict__ Wqkh, __half* __restrict__ Wqkl,
                       __half* __restrict__ Wvh, __half* __restrict__ Woh) {
    int idx = blockIdx.x * blockDim.x + threadIdx.x;
    if (idx >= 524288) return;
    int task = blockIdx.y;
    int st = task & 1;
    if (task < 2) {
        const float* Wq = st ? Wqp : Wqn;
        const float* Wk = st ? Wkp : Wkn;
        int j = idx >> 9, d = idx & 511;
        int jj = j & 511;
        float v;
        if (j < 512)
            v = Wq[((size_t)((jj >> 6) * 512 + d)) * 64 + (jj & 63)] * 0.125f;
        else
            v = Wk[((size_t)((jj >> 6) * 512 + d)) * 64 + (jj & 63)];
        __half h = __float2half_rn(v);
        Wqkh[(size_t)st * WSTR + idx] = h;
        Wqkl[(size_t)st * WSTR + idx] = __float2half_rn(v - __half2float(h));
    } else if (task < 4) {
        const float* Wv = st ? Wvp : Wvn;
        int j = idx >> 9, d = idx & 511;
        Wvh[(size_t)st * WSTR + idx] =
            __float2half_rn(Wv[((size_t)((j >> 6) * 512 + d)) * 64 + (j & 63)]);
    } else {
        const float* Wo = st ? Wop : Won;
        int e = idx >> 10, j = idx & 1023;
        Woh[(size_t)st * WSTR + idx] = __float2half_rn(Wo[(size_t)j * 512 + e]);
    }
}

__global__ void cvt_pair(const float* __restrict__ Xn, const float* __restrict__ Xp,
                         __half* __restrict__ Yh, __half* __restrict__ Yl) {
    int i = blockIdx.x * blockDim.x + threadIdx.x;
    if (i >= ROWS * 512 / 4) return;
    int st = blockIdx.y;
    const float* X = st ? Xp : Xn;
    float4 v = ((const float4*)X)[i];
    __half2 h0, l0, h1, l1;
    split2(v.x, v.y, h0, l0);
    split2(v.z, v.w, h1, l1);
    uint2 uh, ul;
    uh.x = *reinterpret_cast<unsigned*>(&h0);
    uh.y = *reinterpret_cast<unsigned*>(&h1);
    ul.x = *reinterpret_cast<unsigned*>(&l0);
    ul.y = *reinterpret_cast<unsigned*>(&l1);
    ((uint2*)(Yh + (size_t)st * XSTR))[i] = uh;
    ((uint2*)(Yl + (size_t)st * XSTR))[i] = ul;
}

// ---------------------------------------------------------------------------
// Host launcher: 6 kernel launches
// ---------------------------------------------------------------------------
extern "C" void kernel_launch(void* const* d_in, const int* in_sizes, int n_in,
                              void* d_out, int out_size) {
    const float* Xn  = (const float*)d_in[0];
    const float* Xp  = (const float*)d_in[1];
    const float* Wqn = (const float*)d_in[2];
    const float* Wqp = (const float*)d_in[3];
    const float* Wkn = (const float*)d_in[4];
    const float* Wkp = (const float*)d_in[5];
    const float* Wvn = (const float*)d_in[6];
    const float* Wvp = (const float*)d_in[7];
    const float* Won = (const float*)d_in[8];
    const float* Wop = (const float*)d_in[9];
    float* out = (float*)d_out;

    __half *Wqkh, *Wqkl, *Wvh, *Woh, *Xh, *Xl, *QKh, *QKl, *Vth, *H;
    cudaGetSymbolAddress((void**)&Wqkh, g_Wqkh);
    cudaGetSymbolAddress((void**)&Wqkl, g_Wqkl);
    cudaGetSymbolAddress((void**)&Wvh,  g_Wvh);
    cudaGetSymbolAddress((void**)&Woh,  g_Woh);
    cudaGetSymbolAddress((void**)&Xh,   g_Xh);
    cudaGetSymbolAddress((void**)&Xl,   g_Xl);
    cudaGetSymbolAddress((void**)&QKh,  g_QKh);
    cudaGetSymbolAddress((void**)&QKl,  g_QKl);
    cudaGetSymbolAddress((void**)&Vth,  g_Vth);
    cudaGetSymbolAddress((void**)&H,    g_H);

    cudaFuncSetAttribute(hgemm, cudaFuncAttributeMaxDynamicSharedMemorySize,
                         GEMM_SMEM);
    cudaFuncSetAttribute(flash_attn, cudaFuncAttributeMaxDynamicSharedMemorySize,
                         FA_SMEM);

    // 1) fused weight prep + input conversion
    prep_w<<<dim3(2048, 6), 256>>>(Wqn, Wkn, Wqp, Wkp, Wvn, Wvp, Won, Wop,
                                   Wqkh, Wqkl, Wvh, Woh);
    cvt_pair<<<dim3(8192, 2), 256>>>(Xn, Xp, Xh, Xl);

    // 2) Q,K projections, 3-term, pair out, both streams (z)
    hgemm<<<dim3(8, 128, 2), 256, GEMM_SMEM>>>(
        Xh, Xl, Xh, 0, XSTR, 512,
        Wqkh, Wqkh, Wqkl, 0, WSTR, 512,
        QKh, QKl, 0, QKSTR, 1024, 512, 3, 4, 0);

    // 3) V transposed, 1-term, mode 7 (remap, halfoff = 64*z), both streams
    hgemm<<<dim3(128, 8, 2), 256, GEMM_SMEM>>>(
        Wvh, nullptr, nullptr, 0, WSTR, 512,
        Xh, nullptr, nullptr, 0, XSTR, 512,
        Vth, nullptr, 0, 0, ROWS, 512, 1, 7, 64);

    // 4) fused flash attention, both softmax streams (z)
    flash_attn<<<dim3(8, 128, 2), 512, FA_SMEM>>>(
        QKh, QKl, Vth, H, H + QKSTR);

    // 5) output projections, 1-term, fp32 out, both streams (z)
    hgemm<<<dim3(4, 128, 2), 256, GEMM_SMEM>>>(
        H, nullptr, nullptr, 0, HSTR, 1024,
        Woh, nullptr, nullptr, 0, WSTR, 1024,
        out, nullptr, 0, OSTR, 512, 1024, 1, 1, 0);
}

// round 12
// speedup vs baseline: 1.3412x; 1.2696x over previous
#include <cuda_runtime.h>
#include <cuda_fp16.h>

// ===========================================================================
// B=16, N=1024, D=512, H=8, dk=64. ROWS=16384.
// HMMA (mma.sync m16n8k16), fp32 accum, split-fp16 where precision needs it:
//   QK proj: 3-term (Xh*Wh + Xl*Wh + Xh*Wl), pair out
//   S      : 2-term (Qh*Kh + Ql*Kh); flash with REGISTER-RESIDENT softmax
//   V proj : 1-term, out proj: 1-term, PV: V-hi only
// hgemm: 256 threads, 64x32 warp tiles. flash: 256 threads, FA2-style.
// ===========================================================================
#define ROWS 16384
#define PADK 72
#define TILEB (128 * PADK * 2)
#define GEMM_SMEM (4 * TILEB)

#define XSTR  ((long long)ROWS * 512)
#define WSTR  (524288LL)
#define QKSTR ((long long)ROWS * 1024)
#define HSTR  ((long long)ROWS * 1024)
#define OSTR  ((long long)ROWS * 512)

// Flash smem layout (bytes): Qh 18432 | Ql 18432 | 2 x (Kh 9216 + V 18432)
#define NKT    16
#define OFF_Q  0
#define OFF_KV 36864
#define KVBUF  27648
#define FA_SMEM 92160

// ---------------------------------------------------------------------------
// Static device scratch
// ---------------------------------------------------------------------------
__device__ __half g_Wqkh[2][524288], g_Wqkl[2][524288];
__device__ __half g_Wvh [2][524288];
__device__ __half g_Woh [2][524288];
__device__ __half g_Xh  [2][8388608], g_Xl[2][8388608];
__device__ __half g_QKh [2][16777216], g_QKl[2][16777216];
__device__ __half g_Vth [2][16777216];
__device__ __half g_H   [2][16777216];

// ---------------------------------------------------------------------------
// PTX helpers
// ---------------------------------------------------------------------------
__device__ __forceinline__ unsigned smem_u32(const void* p) {
    unsigned a;
    asm("{ .reg .u64 t; cvta.to.shared.u64 t, %1; cvt.u32.u64 %0, t; }"
        : "=r"(a) : "l"(p));
    return a;
}
__device__ __forceinline__ void cpasync16(unsigned s, const void* g) {
    asm volatile("cp.async.cg.shared.global [%0], [%1], 16;" :: "r"(s), "l"(g));
}
__device__ __forceinline__ void cp_commit() {
    asm volatile("cp.async.commit_group;" ::: "memory");
}
__device__ __forceinline__ void cp_wait0() {
    asm volatile("cp.async.wait_group 0;" ::: "memory");
}
__device__ __forceinline__ void ldm4(unsigned& r0, unsigned& r1, unsigned& r2,
                                     unsigned& r3, unsigned a) {
    asm volatile("ldmatrix.sync.aligned.m8n8.x4.shared.b16 {%0,%1,%2,%3}, [%4];"
                 : "=r"(r0), "=r"(r1), "=r"(r2), "=r"(r3) : "r"(a));
}
__device__ __forceinline__ void mma16816(float* c, const unsigned* a,
                                         const unsigned* b) {
    asm volatile(
        "mma.sync.aligned.m16n8k16.row.col.f32.f16.f16.f32 "
        "{%0,%1,%2,%3}, {%4,%5,%6,%7}, {%8,%9}, {%0,%1,%2,%3};"
        : "+f"(c[0]), "+f"(c[1]), "+f"(c[2]), "+f"(c[3])
        : "r"(a[0]), "r"(a[1]), "r"(a[2]), "r"(a[3]), "r"(b[0]), "r"(b[1]));
}
__device__ __forceinline__ void split2(float v0, float v1, __half2& hi, __half2& lo) {
    __half h0 = __float2half_rn(v0), h1 = __float2half_rn(v1);
    __half l0 = __float2half_rn(v0 - __half2float(h0));
    __half l1 = __float2half_rn(v1 - __half2float(h1));
    hi = __halves2half2(h0, h1);
    lo = __halves2half2(l0, l1);
}
__device__ __forceinline__ unsigned h2bits(float a, float b) {
    __half2 t = __floats2half2_rn(a, b);
    return *reinterpret_cast<unsigned*>(&t);
}

// ---------------------------------------------------------------------------
// Multi-term HMMA GEMM (R11-proven): 256 threads, 64x32 warp tiles.
// modes: 1 fp32 | 4 fp16 pair | 7 fp16 + V row remap (halfoff*zb).
// ---------------------------------------------------------------------------
__global__ __launch_bounds__(256, 2)
void hgemm(const __half* __restrict__ A0, const __half* __restrict__ A1,
           const __half* __restrict__ A2,
           long long sAh, long long sAb, int lda,
           const __half* __restrict__ B0, const __half* __restrict__ B1,
           const __half* __restrict__ B2,
           long long sBh, long long sBb, int ldb,
           void* __restrict__ C0, void* __restrict__ C1,
           long long sCh, long long sCb, int ldc,
           int Kper, int nterm, int mode, int halfoff) {
    extern __shared__ __align__(16) char smem[];
    const unsigned smA = smem_u32(smem);
    const unsigned smB = smA + 2 * TILEB;

    const int tid = threadIdx.x;
    const int wid = tid >> 5, lane = tid & 31;
    const int wm = wid & 1, wn = wid >> 1;

    const int zh = (int)(blockIdx.z >> 4), zb = (int)(blockIdx.z & 15);
    const long long aoff = sAh * zh + sAb * zb + (long long)(blockIdx.y * 128) * lda;
    const long long boff = sBh * zh + sBb * zb + (long long)(blockIdx.x * 128) * ldb;
    const __half* At[3] = {A0 + aoff, A1 ? A1 + aoff : A0, A2 ? A2 + aoff : A0};
    const __half* Bt[3] = {B0 + boff, B1 ? B1 + boff : B0, B2 ? B2 + boff : B0};

    int trA[4], trB[4];
    unsigned so[4];
#pragma unroll
    for (int i = 0; i < 4; i++) {
        int c = tid + i * 256;
        int r = c >> 3, s = c & 7;
        trA[i] = r * lda + s * 8;
        trB[i] = r * ldb + s * 8;
        so[i] = (unsigned)(r * PADK + s * 8) * 2;
    }

    const int T = Kper >> 6;
    const int TT = nterm * T;

#define LOAD_TILE(g, bf)                                                      \
    do {                                                                      \
        int t_ = ((g) >= T) + ((g) >= 2 * T);                                 \
        int kk_ = (g) - t_ * T;                                               \
        const __half* ap = At[t_] + kk_ * 64;                                 \
        const __half* bp = Bt[t_] + kk_ * 64;                                 \
        unsigned sa = smA + (bf) * TILEB;                                     \
        unsigned sbm = smB + (bf) * TILEB;                                    \
        _Pragma("unroll")                                                     \
        for (int i_ = 0; i_ < 4; i_++) {                                      \
            cpasync16(sa + so[i_], ap + trA[i_]);                             \
            cpasync16(sbm + so[i_], bp + trB[i_]);                            \
        }                                                                     \
        cp_commit();                                                          \
    } while (0)

    LOAD_TILE(0, 0);

    float acc[4][4][4];
#pragma unroll
    for (int i = 0; i < 4; i++)
#pragma unroll
        for (int j = 0; j < 4; j++)
#pragma unroll
            for (int k = 0; k < 4; k++) acc[i][j][k] = 0.f;

    const int sub = lane >> 3, r8 = lane & 7;

    for (int g = 0; g < TT; g++) {
        const int bf = g & 1;
        cp_wait0();
        __syncthreads();
        if (g + 1 < TT) LOAD_TILE(g + 1, bf ^ 1);

        const unsigned ab = smA + bf * TILEB;
        const unsigned bb = smB + bf * TILEB;
#pragma unroll
        for (int ks = 0; ks < 4; ks++) {
            const int k0 = ks * 16;
            unsigned a[4][4];
#pragma unroll
            for (int mi = 0; mi < 4; mi++) {
                int mrow = wm * 64 + mi * 16 + r8 + (sub & 1) * 8;
                int mcol = k0 + (sub >> 1) * 8;
                ldm4(a[mi][0], a[mi][1], a[mi][2], a[mi][3],
                     ab + (unsigned)(mrow * PADK + mcol) * 2);
            }
            unsigned b[4][2];
#pragma unroll
            for (int np = 0; np < 2; np++) {
                int nrow = wn * 32 + np * 16 + r8 + (sub >> 1) * 8;
                int kcol = k0 + (sub & 1) * 8;
                unsigned q0, q1, q2, q3;
                ldm4(q0, q1, q2, q3, bb + (unsigned)(nrow * PADK + kcol) * 2);
                b[np * 2][0] = q0; b[np * 2][1] = q1;
                b[np * 2 + 1][0] = q2; b[np * 2 + 1][1] = q3;
            }
#pragma unroll
            for (int mi = 0; mi < 4; mi++)
#pragma unroll
                for (int ni = 0; ni < 4; ni++)
                    mma16816(acc[mi][ni], a[mi], b[ni]);
        }
        __syncthreads();
    }
#undef LOAD_TILE

    const int trow = lane >> 2, tcol = (lane & 3) * 2;
    const long long coff = sCh * zh + sCb * zb;

#pragma unroll
    for (int mi = 0; mi < 4; mi++) {
#pragma unroll
        for (int ni = 0; ni < 4; ni++) {
            int rg = blockIdx.y * 128 + wm * 64 + mi * 16 + trow;
            int cg = blockIdx.x * 128 + wn * 32 + ni * 8 + tcol;
            float* ac = acc[mi][ni];
            if (mode == 1) {
                float* p0 = (float*)C0 + coff + (size_t)rg * ldc + cg;
                float* p1 = (float*)C0 + coff + (size_t)(rg + 8) * ldc + cg;
                *(float2*)p0 = make_float2(ac[0], ac[1]);
                *(float2*)p1 = make_float2(ac[2], ac[3]);
            } else if (mode == 4) {
                __half2 h, l;
                size_t o0 = coff + (size_t)rg * ldc + cg;
                size_t o1 = coff + (size_t)(rg + 8) * ldc + cg;
                split2(ac[0], ac[1], h, l);
                *(__half2*)((__half*)C0 + o0) = h;
                *(__half2*)((__half*)C1 + o0) = l;
                split2(ac[2], ac[3], h, l);
                *(__half2*)((__half*)C0 + o1) = h;
                *(__half2*)((__half*)C1 + o1) = l;
            } else {
                int ho = halfoff * zb;
                int ra = ((rg >> 6) << 7) + (rg & 63) + ho;
                int rb0 = rg + 8;
                int rb = ((rb0 >> 6) << 7) + (rb0 & 63) + ho;
                *(__half2*)((__half*)C0 + (size_t)ra * ldc + cg) =
                    __floats2half2_rn(ac[0], ac[1]);
                *(__half2*)((__half*)C0 + (size_t)rb * ldc + cg) =
                    __floats2half2_rn(ac[2], ac[3]);
            }
        }
    }
}

// ---------------------------------------------------------------------------
// Flash attention, FA2-style register softmax. 256 threads, 8 warps.
// Each warp: 16 q-rows, S = 16x64 (2-term), PV = 16x128.
// S C-frags repack directly into P A-frags (no S/P smem roundtrip).
// ---------------------------------------------------------------------------
__global__ __launch_bounds__(256, 1)
void flash_attn(const __half* __restrict__ QKhB, const __half* __restrict__ QKlB,
                const __half* __restrict__ VhB,
                __half* __restrict__ H0B, __half* __restrict__ H1B) {
    extern __shared__ __align__(16) char smem[];
    const unsigned sb = smem_u32(smem);

    const int tid = threadIdx.x, wid = tid >> 5, lane = tid & 31;
    const int sub = lane >> 3, r8 = lane & 7;
    const int trow = lane >> 2, tq2 = (lane & 3) * 2;
    const int qt = blockIdx.x, z = blockIdx.y;
    const int h = z >> 4, b = z & 15;
    const int s = blockIdx.z;

    const __half* QKh = QKhB + (size_t)s * QKSTR;
    const __half* QKl = QKlB + (size_t)s * QKSTR;
    const __half* Vh  = VhB  + (size_t)s * 16777216;
    __half* C0 = H0B + s * 64;
    __half* C1 = H1B + s * 64;

    // Q loads (hi+lo): 4 x 16B chunks per thread per matrix
    {
        const size_t rbase = (size_t)(b << 10) + qt * 128;
#pragma unroll
        for (int i = 0; i < 4; i++) {
            int c = tid + i * 256;
            int r = c >> 3, sc = c & 7;
            unsigned sof = (unsigned)(r * PADK + sc * 8) * 2;
            size_t go = (rbase + r) * 1024 + h * 64 + sc * 8;
            cpasync16(sb + OFF_Q + sof, QKh + go);
            cpasync16(sb + OFF_Q + 18432 + sof, QKl + go);
        }
    }

#define LOAD_KV(kt, bi)                                                       \
    do {                                                                      \
        unsigned kb = sb + OFF_KV + (bi) * KVBUF;                             \
        _Pragma("unroll")                                                     \
        for (int i_ = 0; i_ < 2; i_++) {                                      \
            int c_ = tid + i_ * 256;                                          \
            int r_ = c_ >> 3, sc_ = c_ & 7;                                   \
            cpasync16(kb + (unsigned)(r_ * PADK + sc_ * 8) * 2,               \
                      QKh + ((size_t)(b << 10) + (kt) * 64 + r_) * 1024 +     \
                          512 + h * 64 + sc_ * 8);                            \
        }                                                                     \
        _Pragma("unroll")                                                     \
        for (int i_ = 0; i_ < 4; i_++) {                                      \
            int c_ = tid + i_ * 256;                                          \
            int r_ = c_ >> 3, sc_ = c_ & 7;                                   \
            cpasync16(kb + 9216 + (unsigned)(r_ * PADK + sc_ * 8) * 2,        \
                      Vh + (size_t)(h * 128 + r_) * 16384 +                   \
                          (size_t)(b << 10) + (kt) * 64 + sc_ * 8);           \
        }                                                                     \
        cp_commit();                                                          \
    } while (0)

    LOAD_KV(0, 0);
    cp_wait0();

    float O[16][4];
#pragma unroll
    for (int i = 0; i < 16; i++)
#pragma unroll
        for (int j = 0; j < 4; j++) O[i][j] = 0.f;
    float m0 = -1e30f, m1 = -1e30f, l0 = 0.f, l1 = 0.f;

    for (int kt = 0; kt < NKT; kt++) {
        const int bi = kt & 1;
        if (kt) cp_wait0();
        __syncthreads();
        if (kt + 1 < NKT) LOAD_KV(kt + 1, bi ^ 1);

        const unsigned Kb = sb + OFF_KV + bi * KVBUF;
        const unsigned Vb = Kb + 9216;

        // ---- S: warp tile 16 rows x 64 keys, 2 terms ----
        float sc[8][4];
#pragma unroll
        for (int t = 0; t < 8; t++)
#pragma unroll
            for (int j = 0; j < 4; j++) sc[t][j] = 0.f;

#pragma unroll
        for (int ks = 0; ks < 4; ks++) {
            const int k0 = ks * 16;
            unsigned ah[4], al[4];
            unsigned offa = (unsigned)((wid * 16 + r8 + (sub & 1) * 8) * PADK +
                                       k0 + (sub >> 1) * 8) * 2;
            ldm4(ah[0], ah[1], ah[2], ah[3], sb + OFF_Q + offa);
            ldm4(al[0], al[1], al[2], al[3], sb + OFF_Q + 18432 + offa);
            unsigned bk[8][2];
#pragma unroll
            for (int nb = 0; nb < 4; nb++) {
                unsigned offb = (unsigned)((nb * 16 + r8 + (sub >> 1) * 8) * PADK +
                                           k0 + (sub & 1) * 8) * 2;
                unsigned q0, q1, q2, q3;
                ldm4(q0, q1, q2, q3, Kb + offb);
                bk[2 * nb][0] = q0; bk[2 * nb][1] = q1;
                bk[2 * nb + 1][0] = q2; bk[2 * nb + 1][1] = q3;
            }
#pragma unroll
            for (int t = 0; t < 8; t++) {
                mma16816(sc[t], ah, bk[t]);
                mma16816(sc[t], al, bk[t]);
            }
        }

        // ---- register softmax (rows trow and trow+8) ----
        float mt0 = sc[0][0], mt1 = sc[0][2];
#pragma unroll
        for (int t = 0; t < 8; t++) {
            mt0 = fmaxf(mt0, fmaxf(sc[t][0], sc[t][1]));
            mt1 = fmaxf(mt1, fmaxf(sc[t][2], sc[t][3]));
        }
        mt0 = fmaxf(mt0, __shfl_xor_sync(~0u, mt0, 1));
        mt0 = fmaxf(mt0, __shfl_xor_sync(~0u, mt0, 2));
        mt1 = fmaxf(mt1, __shfl_xor_sync(~0u, mt1, 1));
        mt1 = fmaxf(mt1, __shfl_xor_sync(~0u, mt1, 2));
        float mn0 = fmaxf(m0, mt0), mn1 = fmaxf(m1, mt1);
        float f0 = __expf(m0 - mn0), f1 = __expf(m1 - mn1);
        float sum0 = 0.f, sum1 = 0.f;
        unsigned pf[4][4];   // P A-frags for the 4 k16 chunks
#pragma unroll
        for (int kk = 0; kk < 4; kk++) {
            float e00 = __expf(sc[2 * kk][0] - mn0);
            float e01 = __expf(sc[2 * kk][1] - mn0);
            float e02 = __expf(sc[2 * kk][2] - mn1);
            float e03 = __expf(sc[2 * kk][3] - mn1);
            float e10 = __expf(sc[2 * kk + 1][0] - mn0);
            float e11 = __expf(sc[2 * kk + 1][1] - mn0);
            float e12 = __expf(sc[2 * kk + 1][2] - mn1);
            float e13 = __expf(sc[2 * kk + 1][3] - mn1);
            sum0 += e00 + e01 + e10 + e11;
            sum1 += e02 + e03 + e12 + e13;
            pf[kk][0] = h2bits(e00, e01);
            pf[kk][1] = h2bits(e02, e03);
            pf[kk][2] = h2bits(e10, e11);
            pf[kk][3] = h2bits(e12, e13);
        }
        sum0 += __shfl_xor_sync(~0u, sum0, 1);
        sum0 += __shfl_xor_sync(~0u, sum0, 2);
        sum1 += __shfl_xor_sync(~0u, sum1, 1);
        sum1 += __shfl_xor_sync(~0u, sum1, 2);
        l0 = l0 * f0 + sum0;  m0 = mn0;
        l1 = l1 * f1 + sum1;  m1 = mn1;

        // ---- rescale O, then PV: 16 rows x 128 cols, K = 64 keys ----
#pragma unroll
        for (int ni = 0; ni < 16; ni++) {
            O[ni][0] *= f0; O[ni][1] *= f0;
            O[ni][2] *= f1; O[ni][3] *= f1;
        }
#pragma unroll
        for (int kk = 0; kk < 4; kk++) {
            const int k0 = kk * 16;
            unsigned bv[16][2];
#pragma unroll
            for (int nb = 0; nb < 8; nb++) {
                unsigned offv = (unsigned)((nb * 16 + r8 + (sub >> 1) * 8) * PADK +
                                           k0 + (sub & 1) * 8) * 2;
                unsigned q0, q1, q2, q3;
                ldm4(q0, q1, q2, q3, Vb + offv);
                bv[2 * nb][0] = q0; bv[2 * nb][1] = q1;
                bv[2 * nb + 1][0] = q2; bv[2 * nb + 1][1] = q3;
            }
#pragma unroll
            for (int ni = 0; ni < 16; ni++)
                mma16816(O[ni], pf[kk], bv[ni]);
        }
    }
#undef LOAD_KV

    // ---- epilogue: normalize, split node/pos cols, fp16 out ----
    const float inv0 = 1.f / l0, inv1 = 1.f / l1;
    const long long coff = 128LL * h + 1048576LL * b;
    const int rg0 = qt * 128 + wid * 16 + trow, rg1 = rg0 + 8;
#pragma unroll
    for (int ni = 0; ni < 16; ni++) {
        int cg = ni * 8 + tq2;
        __half* base = (cg < 64) ? C0 : C1;
        int cl = cg & 63;
        *(__half2*)(base + coff + (size_t)rg0 * 1024 + cl) =
            __floats2half2_rn(O[ni][0] * inv0, O[ni][1] * inv0);
        *(__half2*)(base + coff + (size_t)rg1 * 1024 + cl) =
            __floats2half2_rn(O[ni][2] * inv1, O[ni][3] * inv1);
    }
}

// ---------------------------------------------------------------------------
// Fused weight prep + input conversion (unchanged)
// ---------------------------------------------------------------------------
__global__ void prep_w(const float* __restrict__ Wqn, const float* __restrict__ Wkn,
                       const float* __restrict__ Wqp, const float* __restrict__ Wkp,
                       const float* __restrict__ Wvn, const float* __restrict__ Wvp,
                       const float* __restrict__ Won, const float* __restrict__ Wop,
                       __half* __restrict__ Wqkh, __half* __restrict__ Wqkl,
                       __half* __restrict__ Wvh, __half* __restrict__ Woh) {
    int idx = blockIdx.x * blockDim.x + threadIdx.x;
    if (idx >= 524288) return;
    int task = blockIdx.y;
    int st = task & 1;
    if (task < 2) {
        const float* Wq = st ? Wqp : Wqn;
        const float* Wk = st ? Wkp : Wkn;
        int j = idx >> 9, d = idx & 511;
        int jj = j & 511;
        float v;
        if (j < 512)
            v = Wq[((size_t)((jj >> 6) * 512 + d)) * 64 + (jj & 63)] * 0.125f;
        else
            v = Wk[((size_t)((jj >> 6) * 512 + d)) * 64 + (jj & 63)];
        __half h = __float2half_rn(v);
        Wqkh[(size_t)st * WSTR + idx] = h;
        Wqkl[(size_t)st * WSTR + idx] = __float2half_rn(v - __half2float(h));
    } else if (task < 4) {
        const float* Wv = st ? Wvp : Wvn;
        int j = idx >> 9, d = idx & 511;
        Wvh[(size_t)st * WSTR + idx] =
            __float2half_rn(Wv[((size_t)((j >> 6) * 512 + d)) * 64 + (j & 63)]);
    } else {
        const float* Wo = st ? Wop : Won;
        int e = idx >> 10, j = idx & 1023;
        Woh[(size_t)st * WSTR + idx] = __float2half_rn(Wo[(size_t)j * 512 + e]);
    }
}

__global__ void cvt_pair(const float* __restrict__ Xn, const float* __restrict__ Xp,
                         __half* __restrict__ Yh, __half* __restrict__ Yl) {
    int i = blockIdx.x * blockDim.x + threadIdx.x;
    if (i >= ROWS * 512 / 4) return;
    int st = blockIdx.y;
    const float* X = st ? Xp : Xn;
    float4 v = ((const float4*)X)[i];
    __half2 h0, l0, h1, l1;
    split2(v.x, v.y, h0, l0);
    split2(v.z, v.w, h1, l1);
    uint2 uh, ul;
    uh.x = *reinterpret_cast<unsigned*>(&h0);
    uh.y = *reinterpret_cast<unsigned*>(&h1);
    ul.x = *reinterpret_cast<unsigned*>(&l0);
    ul.y = *reinterpret_cast<unsigned*>(&l1);
    ((uint2*)(Yh + (size_t)st * XSTR))[i] = uh;
    ((uint2*)(Yl + (size_t)st * XSTR))[i] = ul;
}

// ---------------------------------------------------------------------------
// Host launcher: 6 kernel launches
// ---------------------------------------------------------------------------
extern "C" void kernel_launch(void* const* d_in, const int* in_sizes, int n_in,
                              void* d_out, int out_size) {
    const float* Xn  = (const float*)d_in[0];
    const float* Xp  = (const float*)d_in[1];
    const float* Wqn = (const float*)d_in[2];
    const float* Wqp = (const float*)d_in[3];
    const float* Wkn = (const float*)d_in[4];
    const float* Wkp = (const float*)d_in[5];
    const float* Wvn = (const float*)d_in[6];
    const float* Wvp = (const float*)d_in[7];
    const float* Won = (const float*)d_in[8];
    const float* Wop = (const float*)d_in[9];
    float* out = (float*)d_out;

    __half *Wqkh, *Wqkl, *Wvh, *Woh, *Xh, *Xl, *QKh, *QKl, *Vth, *H;
    cudaGetSymbolAddress((void**)&Wqkh, g_Wqkh);
    cudaGetSymbolAddress((void**)&Wqkl, g_Wqkl);
    cudaGetSymbolAddress((void**)&Wvh,  g_Wvh);
    cudaGetSymbolAddress((void**)&Woh,  g_Woh);
    cudaGetSymbolAddress((void**)&Xh,   g_Xh);
    cudaGetSymbolAddress((void**)&Xl,   g_Xl);
    cudaGetSymbolAddress((void**)&QKh,  g_QKh);
    cudaGetSymbolAddress((void**)&QKl,  g_QKl);
    cudaGetSymbolAddress((void**)&Vth,  g_Vth);
    cudaGetSymbolAddress((void**)&H,    g_H);

    cudaFuncSetAttribute(hgemm, cudaFuncAttributeMaxDynamicSharedMemorySize,
                         GEMM_SMEM);
    cudaFuncSetAttribute(flash_attn, cudaFuncAttributeMaxDynamicSharedMemorySize,
                         FA_SMEM);

    // 1) fused weight prep + input conversion
    prep_w<<<dim3(2048, 6), 256>>>(Wqn, Wkn, Wqp, Wkp, Wvn, Wvp, Won, Wop,
                                   Wqkh, Wqkl, Wvh, Woh);
    cvt_pair<<<dim3(8192, 2), 256>>>(Xn, Xp, Xh, Xl);

    // 2) Q,K projections, 3-term, pair out, both streams (z)
    hgemm<<<dim3(8, 128, 2), 256, GEMM_SMEM>>>(
        Xh, Xl, Xh, 0, XSTR, 512,
        Wqkh, Wqkh, Wqkl, 0, WSTR, 512,
        QKh, QKl, 0, QKSTR, 1024, 512, 3, 4, 0);

    // 3) V transposed, 1-term, mode 7 (remap, halfoff = 64*z), both streams
    hgemm<<<dim3(128, 8, 2), 256, GEMM_SMEM>>>(
        Wvh, nullptr, nullptr, 0, WSTR, 512,
        Xh, nullptr, nullptr, 0, XSTR, 512,
        Vth, nullptr, 0, 0, ROWS, 512, 1, 7, 64);

    // 4) flash attention (FA2 register softmax), both streams (z)
    flash_attn<<<dim3(8, 128, 2), 256, FA_SMEM>>>(
        QKh, QKl, Vth, H, H + QKSTR);

    // 5) output projections, 1-term, fp32 out, both streams (z)
    hgemm<<<dim3(4, 128, 2), 256, GEMM_SMEM>>>(
        H, nullptr, nullptr, 0, HSTR, 1024,
        Woh, nullptr, nullptr, 0, WSTR, 1024,
        out, nullptr, 0, OSTR, 512, 1024, 1, 1, 0);
}

// round 13
// speedup vs baseline: 1.3862x; 1.0336x over previous
#include <cuda_runtime.h>
#include <cuda_fp16.h>

// ===========================================================================
// B=16, N=1024, D=512, H=8, dk=64. ROWS=16384.
// HMMA (mma.sync m16n8k16), fp32 accum, split-fp16 where precision needs it:
//   QK proj: 3-term (Xh*Wh + Xl*Wh + Xh*Wl), pair out
//   S      : 2-term (Qh*Kh + Ql*Kh); flash with register-resident softmax
//   V proj : 1-term, out proj: 1-term, PV: V-hi only
// hgemm: 128 threads, 4 warps of 64x64 (LDSM:MMA = 0.25).
// flash: 256 threads, FA2-style (R12-proven).
// ===========================================================================
#define ROWS 16384
#define PADK 72
#define TILEB (128 * PADK * 2)
#define GEMM_SMEM (4 * TILEB)

#define XSTR  ((long long)ROWS * 512)
#define WSTR  (524288LL)
#define QKSTR ((long long)ROWS * 1024)
#define HSTR  ((long long)ROWS * 1024)
#define OSTR  ((long long)ROWS * 512)

// Flash smem layout (bytes): Qh 18432 | Ql 18432 | 2 x (Kh 9216 + V 18432)
#define NKT    16
#define OFF_Q  0
#define OFF_KV 36864
#define KVBUF  27648
#define FA_SMEM 92160

// ---------------------------------------------------------------------------
// Static device scratch
// ---------------------------------------------------------------------------
__device__ __half g_Wqkh[2][524288], g_Wqkl[2][524288];
__device__ __half g_Wvh [2][524288];
__device__ __half g_Woh [2][524288];
__device__ __half g_Xh  [2][8388608], g_Xl[2][8388608];
__device__ __half g_QKh [2][16777216], g_QKl[2][16777216];
__device__ __half g_Vth [2][16777216];
__device__ __half g_H   [2][16777216];

// ---------------------------------------------------------------------------
// PTX helpers
// ---------------------------------------------------------------------------
__device__ __forceinline__ unsigned smem_u32(const void* p) {
    unsigned a;
    asm("{ .reg .u64 t; cvta.to.shared.u64 t, %1; cvt.u32.u64 %0, t; }"
        : "=r"(a) : "l"(p));
    return a;
}
__device__ __forceinline__ void cpasync16(unsigned s, const void* g) {
    asm volatile("cp.async.cg.shared.global [%0], [%1], 16;" :: "r"(s), "l"(g));
}
__device__ __forceinline__ void cp_commit() {
    asm volatile("cp.async.commit_group;" ::: "memory");
}
__device__ __forceinline__ void cp_wait0() {
    asm volatile("cp.async.wait_group 0;" ::: "memory");
}
__device__ __forceinline__ void ldm4(unsigned& r0, unsigned& r1, unsigned& r2,
                                     unsigned& r3, unsigned a) {
    asm volatile("ldmatrix.sync.aligned.m8n8.x4.shared.b16 {%0,%1,%2,%3}, [%4];"
                 : "=r"(r0), "=r"(r1), "=r"(r2), "=r"(r3) : "r"(a));
}
__device__ __forceinline__ void mma16816(float* c, const unsigned* a,
                                         const unsigned* b) {
    asm volatile(
        "mma.sync.aligned.m16n8k16.row.col.f32.f16.f16.f32 "
        "{%0,%1,%2,%3}, {%4,%5,%6,%7}, {%8,%9}, {%0,%1,%2,%3};"
        : "+f"(c[0]), "+f"(c[1]), "+f"(c[2]), "+f"(c[3])
        : "r"(a[0]), "r"(a[1]), "r"(a[2]), "r"(a[3]), "r"(b[0]), "r"(b[1]));
}
__device__ __forceinline__ void split2(float v0, float v1, __half2& hi, __half2& lo) {
    __half h0 = __float2half_rn(v0), h1 = __float2half_rn(v1);
    __half l0 = __float2half_rn(v0 - __half2float(h0));
    __half l1 = __float2half_rn(v1 - __half2float(h1));
    hi = __halves2half2(h0, h1);
    lo = __halves2half2(l0, l1);
}
__device__ __forceinline__ unsigned h2bits(float a, float b) {
    __half2 t = __floats2half2_rn(a, b);
    return *reinterpret_cast<unsigned*>(&t);
}

// ---------------------------------------------------------------------------
// Multi-term HMMA GEMM: 128 threads, 4 warps of 64x64 warp tiles.
// Two-stage cp.async double buffer. blockIdx.z -> zb (stream).
// modes: 1 fp32 | 4 fp16 pair | 7 fp16 + V row remap (halfoff*zb).
// ---------------------------------------------------------------------------
__global__ __launch_bounds__(128, 3)
void hgemm(const __half* __restrict__ A0, const __half* __restrict__ A1,
           const __half* __restrict__ A2,
           long long sAh, long long sAb, int lda,
           const __half* __restrict__ B0, const __half* __restrict__ B1,
           const __half* __restrict__ B2,
           long long sBh, long long sBb, int ldb,
           void* __restrict__ C0, void* __restrict__ C1,
           long long sCh, long long sCb, int ldc,
           int Kper, int nterm, int mode, int halfoff) {
    extern __shared__ __align__(16) char smem[];
    const unsigned smA = smem_u32(smem);
    const unsigned smB = smA + 2 * TILEB;

    const int tid = threadIdx.x;
    const int wid = tid >> 5, lane = tid & 31;
    const int wm = wid & 1, wn = wid >> 1;   // 2 x 2 warps of 64x64

    const int zh = (int)(blockIdx.z >> 4), zb = (int)(blockIdx.z & 15);
    const long long aoff = sAh * zh + sAb * zb + (long long)(blockIdx.y * 128) * lda;
    const long long boff = sBh * zh + sBb * zb + (long long)(blockIdx.x * 128) * ldb;
    const __half* At[3] = {A0 + aoff, A1 ? A1 + aoff : A0, A2 ? A2 + aoff : A0};
    const __half* Bt[3] = {B0 + boff, B1 ? B1 + boff : B0, B2 ? B2 + boff : B0};

    // loader: 1024 x 16B chunks per matrix, 8 per thread (128 threads)
    const int r0 = tid >> 3, s0 = tid & 7;
    const unsigned sbase0 = (unsigned)(r0 * PADK + s0 * 8) * 2;
    const int ta0 = r0 * lda + s0 * 8, tb0 = r0 * ldb + s0 * 8;

    const int T = Kper >> 6;
    const int TT = nterm * T;

#define LOAD_TILE(g, bf)                                                      \
    do {                                                                      \
        int t_ = ((g) >= T) + ((g) >= 2 * T);                                 \
        int kk_ = (g) - t_ * T;                                               \
        const __half* ap = At[t_] + kk_ * 64;                                 \
        const __half* bp = Bt[t_] + kk_ * 64;                                 \
        unsigned sa = smA + (bf) * TILEB;                                     \
        unsigned sbm = smB + (bf) * TILEB;                                    \
        _Pragma("unroll")                                                     \
        for (int i_ = 0; i_ < 8; i_++) {                                      \
            cpasync16(sa + sbase0 + (unsigned)(i_ * 16 * PADK) * 2,           \
                      ap + ta0 + i_ * 16 * lda);                              \
            cpasync16(sbm + sbase0 + (unsigned)(i_ * 16 * PADK) * 2,          \
                      bp + tb0 + i_ * 16 * ldb);                              \
        }                                                                     \
        cp_commit();                                                          \
    } while (0)

    LOAD_TILE(0, 0);

    float acc[4][8][4];
#pragma unroll
    for (int i = 0; i < 4; i++)
#pragma unroll
        for (int j = 0; j < 8; j++)
#pragma unroll
            for (int k = 0; k < 4; k++) acc[i][j][k] = 0.f;

    const int sub = lane >> 3, r8 = lane & 7;

    for (int g = 0; g < TT; g++) {
        const int bf = g & 1;
        cp_wait0();
        __syncthreads();
        if (g + 1 < TT) LOAD_TILE(g + 1, bf ^ 1);

        const unsigned ab = smA + bf * TILEB;
        const unsigned bb = smB + bf * TILEB;
#pragma unroll
        for (int ks = 0; ks < 4; ks++) {
            const int k0 = ks * 16;
            unsigned a[4][4];
#pragma unroll
            for (int mi = 0; mi < 4; mi++) {
                int mrow = wm * 64 + mi * 16 + r8 + (sub & 1) * 8;
                int mcol = k0 + (sub >> 1) * 8;
                ldm4(a[mi][0], a[mi][1], a[mi][2], a[mi][3],
                     ab + (unsigned)(mrow * PADK + mcol) * 2);
            }
            // B in two halves to cap register liveness
#pragma unroll
            for (int nh = 0; nh < 2; nh++) {
                unsigned b[4][2];
#pragma unroll
                for (int np = 0; np < 2; np++) {
                    int nrow = wn * 64 + nh * 32 + np * 16 + r8 + (sub >> 1) * 8;
                    int kcol = k0 + (sub & 1) * 8;
                    unsigned q0, q1, q2, q3;
                    ldm4(q0, q1, q2, q3, bb + (unsigned)(nrow * PADK + kcol) * 2);
                    b[np * 2][0] = q0; b[np * 2][1] = q1;
                    b[np * 2 + 1][0] = q2; b[np * 2 + 1][1] = q3;
                }
#pragma unroll
                for (int mi = 0; mi < 4; mi++)
#pragma unroll
                    for (int ni = 0; ni < 4; ni++)
                        mma16816(acc[mi][nh * 4 + ni], a[mi], b[ni]);
            }
        }
        __syncthreads();
    }
#undef LOAD_TILE

    const int trow = lane >> 2, tcol = (lane & 3) * 2;
    const long long coff = sCh * zh + sCb * zb;

#pragma unroll
    for (int mi = 0; mi < 4; mi++) {
#pragma unroll
        for (int ni = 0; ni < 8; ni++) {
            int rg = blockIdx.y * 128 + wm * 64 + mi * 16 + trow;
            int cg = blockIdx.x * 128 + wn * 64 + ni * 8 + tcol;
            float* ac = acc[mi][ni];
            if (mode == 1) {
                float* p0 = (float*)C0 + coff + (size_t)rg * ldc + cg;
                float* p1 = (float*)C0 + coff + (size_t)(rg + 8) * ldc + cg;
                *(float2*)p0 = make_float2(ac[0], ac[1]);
                *(float2*)p1 = make_float2(ac[2], ac[3]);
            } else if (mode == 4) {
                __half2 h, l;
                size_t o0 = coff + (size_t)rg * ldc + cg;
                size_t o1 = coff + (size_t)(rg + 8) * ldc + cg;
                split2(ac[0], ac[1], h, l);
                *(__half2*)((__half*)C0 + o0) = h;
                *(__half2*)((__half*)C1 + o0) = l;
                split2(ac[2], ac[3], h, l);
                *(__half2*)((__half*)C0 + o1) = h;
                *(__half2*)((__half*)C1 + o1) = l;
            } else {  // mode 7: single fp16 out + V row remap (halfoff * zb)
                int ho = halfoff * zb;
                int ra = ((rg >> 6) << 7) + (rg & 63) + ho;
                int rb0 = rg + 8;
                int rb = ((rb0 >> 6) << 7) + (rb0 & 63) + ho;
                *(__half2*)((__half*)C0 + (size_t)ra * ldc + cg) =
                    __floats2half2_rn(ac[0], ac[1]);
                *(__half2*)((__half*)C0 + (size_t)rb * ldc + cg) =
                    __floats2half2_rn(ac[2], ac[3]);
            }
        }
    }
}

// ---------------------------------------------------------------------------
// Flash attention, FA2-style register softmax (R12-proven, unchanged).
// ---------------------------------------------------------------------------
__global__ __launch_bounds__(256, 1)
void flash_attn(const __half* __restrict__ QKhB, const __half* __restrict__ QKlB,
                const __half* __restrict__ VhB,
                __half* __restrict__ H0B, __half* __restrict__ H1B) {
    extern __shared__ __align__(16) char smem[];
    const unsigned sb = smem_u32(smem);

    const int tid = threadIdx.x, wid = tid >> 5, lane = tid & 31;
    const int sub = lane >> 3, r8 = lane & 7;
    const int trow = lane >> 2, tq2 = (lane & 3) * 2;
    const int qt = blockIdx.x, z = blockIdx.y;
    const int h = z >> 4, b = z & 15;
    const int s = blockIdx.z;

    const __half* QKh = QKhB + (size_t)s * QKSTR;
    const __half* QKl = QKlB + (size_t)s * QKSTR;
    const __half* Vh  = VhB  + (size_t)s * 16777216;
    __half* C0 = H0B + s * 64;
    __half* C1 = H1B + s * 64;

    {
        const size_t rbase = (size_t)(b << 10) + qt * 128;
#pragma unroll
        for (int i = 0; i < 4; i++) {
            int c = tid + i * 256;
            int r = c >> 3, sc = c & 7;
            unsigned sof = (unsigned)(r * PADK + sc * 8) * 2;
            size_t go = (rbase + r) * 1024 + h * 64 + sc * 8;
            cpasync16(sb + OFF_Q + sof, QKh + go);
            cpasync16(sb + OFF_Q + 18432 + sof, QKl + go);
        }
    }

#define LOAD_KV(kt, bi)                                                       \
    do {                                                                      \
        unsigned kb = sb + OFF_KV + (bi) * KVBUF;                             \
        _Pragma("unroll")                                                     \
        for (int i_ = 0; i_ < 2; i_++) {                                      \
            int c_ = tid + i_ * 256;                                          \
            int r_ = c_ >> 3, sc_ = c_ & 7;                                   \
            cpasync16(kb + (unsigned)(r_ * PADK + sc_ * 8) * 2,               \
                      QKh + ((size_t)(b << 10) + (kt) * 64 + r_) * 1024 +     \
                          512 + h * 64 + sc_ * 8);                            \
        }                                                                     \
        _Pragma("unroll")                                                     \
        for (int i_ = 0; i_ < 4; i_++) {                                      \
            int c_ = tid + i_ * 256;                                          \
            int r_ = c_ >> 3, sc_ = c_ & 7;                                   \
            cpasync16(kb + 9216 + (unsigned)(r_ * PADK + sc_ * 8) * 2,        \
                      Vh + (size_t)(h * 128 + r_) * 16384 +                   \
                          (size_t)(b << 10) + (kt) * 64 + sc_ * 8);           \
        }                                                                     \
        cp_commit();                                                          \
    } while (0)

    LOAD_KV(0, 0);
    cp_wait0();

    float O[16][4];
#pragma unroll
    for (int i = 0; i < 16; i++)
#pragma unroll
        for (int j = 0; j < 4; j++) O[i][j] = 0.f;
    float m0 = -1e30f, m1 = -1e30f, l0 = 0.f, l1 = 0.f;

    for (int kt = 0; kt < NKT; kt++) {
        const int bi = kt & 1;
        if (kt) cp_wait0();
        __syncthreads();
        if (kt + 1 < NKT) LOAD_KV(kt + 1, bi ^ 1);

        const unsigned Kb = sb + OFF_KV + bi * KVBUF;
        const unsigned Vb = Kb + 9216;

        float sc[8][4];
#pragma unroll
        for (int t = 0; t < 8; t++)
#pragma unroll
            for (int j = 0; j < 4; j++) sc[t][j] = 0.f;

#pragma unroll
        for (int ks = 0; ks < 4; ks++) {
            const int k0 = ks * 16;
            unsigned ah[4], al[4];
            unsigned offa = (unsigned)((wid * 16 + r8 + (sub & 1) * 8) * PADK +
                                       k0 + (sub >> 1) * 8) * 2;
            ldm4(ah[0], ah[1], ah[2], ah[3], sb + OFF_Q + offa);
            ldm4(al[0], al[1], al[2], al[3], sb + OFF_Q + 18432 + offa);
            unsigned bk[8][2];
#pragma unroll
            for (int nb = 0; nb < 4; nb++) {
                unsigned offb = (unsigned)((nb * 16 + r8 + (sub >> 1) * 8) * PADK +
                                           k0 + (sub & 1) * 8) * 2;
                unsigned q0, q1, q2, q3;
                ldm4(q0, q1, q2, q3, Kb + offb);
                bk[2 * nb][0] = q0; bk[2 * nb][1] = q1;
                bk[2 * nb + 1][0] = q2; bk[2 * nb + 1][1] = q3;
            }
#pragma unroll
            for (int t = 0; t < 8; t++) {
                mma16816(sc[t], ah, bk[t]);
                mma16816(sc[t], al, bk[t]);
            }
        }

        float mt0 = sc[0][0], mt1 = sc[0][2];
#pragma unroll
        for (int t = 0; t < 8; t++) {
            mt0 = fmaxf(mt0, fmaxf(sc[t][0], sc[t][1]));
            mt1 = fmaxf(mt1, fmaxf(sc[t][2], sc[t][3]));
        }
        mt0 = fmaxf(mt0, __shfl_xor_sync(~0u, mt0, 1));
        mt0 = fmaxf(mt0, __shfl_xor_sync(~0u, mt0, 2));
        mt1 = fmaxf(mt1, __shfl_xor_sync(~0u, mt1, 1));
        mt1 = fmaxf(mt1, __shfl_xor_sync(~0u, mt1, 2));
        float mn0 = fmaxf(m0, mt0), mn1 = fmaxf(m1, mt1);
        float f0 = __expf(m0 - mn0), f1 = __expf(m1 - mn1);
        float sum0 = 0.f, sum1 = 0.f;
        unsigned pf[4][4];
#pragma unroll
        for (int kk = 0; kk < 4; kk++) {
            float e00 = __expf(sc[2 * kk][0] - mn0);
            float e01 = __expf(sc[2 * kk][1] - mn0);
            float e02 = __expf(sc[2 * kk][2] - mn1);
            float e03 = __expf(sc[2 * kk][3] - mn1);
            float e10 = __expf(sc[2 * kk + 1][0] - mn0);
            float e11 = __expf(sc[2 * kk + 1][1] - mn0);
            float e12 = __expf(sc[2 * kk + 1][2] - mn1);
            float e13 = __expf(sc[2 * kk + 1][3] - mn1);
            sum0 += e00 + e01 + e10 + e11;
            sum1 += e02 + e03 + e12 + e13;
            pf[kk][0] = h2bits(e00, e01);
            pf[kk][1] = h2bits(e02, e03);
            pf[kk][2] = h2bits(e10, e11);
            pf[kk][3] = h2bits(e12, e13);
        }
        sum0 += __shfl_xor_sync(~0u, sum0, 1);
        sum0 += __shfl_xor_sync(~0u, sum0, 2);
        sum1 += __shfl_xor_sync(~0u, sum1, 1);
        sum1 += __shfl_xor_sync(~0u, sum1, 2);
        l0 = l0 * f0 + sum0;  m0 = mn0;
        l1 = l1 * f1 + sum1;  m1 = mn1;

#pragma unroll
        for (int ni = 0; ni < 16; ni++) {
            O[ni][0] *= f0; O[ni][1] *= f0;
            O[ni][2] *= f1; O[ni][3] *= f1;
        }
#pragma unroll
        for (int kk = 0; kk < 4; kk++) {
            const int k0 = kk * 16;
            unsigned bv[16][2];
#pragma unroll
            for (int nb = 0; nb < 8; nb++) {
                unsigned offv = (unsigned)((nb * 16 + r8 + (sub >> 1) * 8) * PADK +
                                           k0 + (sub & 1) * 8) * 2;
                unsigned q0, q1, q2, q3;
                ldm4(q0, q1, q2, q3, Vb + offv);
                bv[2 * nb][0] = q0; bv[2 * nb][1] = q1;
                bv[2 * nb + 1][0] = q2; bv[2 * nb + 1][1] = q3;
            }
#pragma unroll
            for (int ni = 0; ni < 16; ni++)
                mma16816(O[ni], pf[kk], bv[ni]);
        }
    }
#undef LOAD_KV

    const float inv0 = 1.f / l0, inv1 = 1.f / l1;
    const long long coff = 128LL * h + 1048576LL * b;
    const int rg0 = qt * 128 + wid * 16 + trow, rg1 = rg0 + 8;
#pragma unroll
    for (int ni = 0; ni < 16; ni++) {
        int cg = ni * 8 + tq2;
        __half* base = (cg < 64) ? C0 : C1;
        int cl = cg & 63;
        *(__half2*)(base + coff + (size_t)rg0 * 1024 + cl) =
            __floats2half2_rn(O[ni][0] * inv0, O[ni][1] * inv0);
        *(__half2*)(base + coff + (size_t)rg1 * 1024 + cl) =
            __floats2half2_rn(O[ni][2] * inv1, O[ni][3] * inv1);
    }
}

// ---------------------------------------------------------------------------
// Fused weight prep + input conversion (unchanged)
// ---------------------------------------------------------------------------
__global__ void prep_w(const float* __restrict__ Wqn, const float* __restrict__ Wkn,
                       const float* __restrict__ Wqp, const float* __restrict__ Wkp,
                       const float* __restrict__ Wvn, const float* __restrict__ Wvp,
                       const float* __restrict__ Won, const float* __restrict__ Wop,
                       __half* __restrict__ Wqkh, __half* __restrict__ Wqkl,
                       __half* __restrict__ Wvh, __half* __restrict__ Woh) {
    int idx = blockIdx.x * blockDim.x + threadIdx.x;
    if (idx >= 524288) return;
    int task = blockIdx.y;
    int st = task & 1;
    if (task < 2) {
        const float* Wq = st ? Wqp : Wqn;
        const float* Wk = st ? Wkp : Wkn;
        int j = idx >> 9, d = idx & 511;
        int jj = j & 511;
        float v;
        if (j < 512)
            v = Wq[((size_t)((jj >> 6) * 512 + d)) * 64 + (jj & 63)] * 0.125f;
        else
            v = Wk[((size_t)((jj >> 6) * 512 + d)) * 64 + (jj & 63)];
        __half h = __float2half_rn(v);
        Wqkh[(size_t)st * WSTR + idx] = h;
        Wqkl[(size_t)st * WSTR + idx] = __float2half_rn(v - __half2float(h));
    } else if (task < 4) {
        const float* Wv = st ? Wvp : Wvn;
        int j = idx >> 9, d = idx & 511;
        Wvh[(size_t)st * WSTR + idx] =
            __float2half_rn(Wv[((size_t)((j >> 6) * 512 + d)) * 64 + (j & 63)]);
    } else {
        const float* Wo = st ? Wop : Won;
        int e = idx >> 10, j = idx & 1023;
        Woh[(size_t)st * WSTR + idx] = __float2half_rn(Wo[(size_t)j * 512 + e]);
    }
}

__global__ void cvt_pair(const float* __restrict__ Xn, const float* __restrict__ Xp,
                         __half* __restrict__ Yh, __half* __restrict__ Yl) {
    int i = blockIdx.x * blockDim.x + threadIdx.x;
    if (i >= ROWS * 512 / 4) return;
    int st = blockIdx.y;
    const float* X = st ? Xp : Xn;
    float4 v = ((const float4*)X)[i];
    __half2 h0, l0, h1, l1;
    split2(v.x, v.y, h0, l0);
    split2(v.z, v.w, h1, l1);
    uint2 uh, ul;
    uh.x = *reinterpret_cast<unsigned*>(&h0);
    uh.y = *reinterpret_cast<unsigned*>(&h1);
    ul.x = *reinterpret_cast<unsigned*>(&l0);
    ul.y = *reinterpret_cast<unsigned*>(&l1);
    ((uint2*)(Yh + (size_t)st * XSTR))[i] = uh;
    ((uint2*)(Yl + (size_t)st * XSTR))[i] = ul;
}

// ---------------------------------------------------------------------------
// Host launcher: 6 kernel launches
// ---------------------------------------------------------------------------
extern "C" void kernel_launch(void* const* d_in, const int* in_sizes, int n_in,
                              void* d_out, int out_size) {
    const float* Xn  = (const float*)d_in[0];
    const float* Xp  = (const float*)d_in[1];
    const float* Wqn = (const float*)d_in[2];
    const float* Wqp = (const float*)d_in[3];
    const float* Wkn = (const float*)d_in[4];
    const float* Wkp = (const float*)d_in[5];
    const float* Wvn = (const float*)d_in[6];
    const float* Wvp = (const float*)d_in[7];
    const float* Won = (const float*)d_in[8];
    const float* Wop = (const float*)d_in[9];
    float* out = (float*)d_out;

    __half *Wqkh, *Wqkl, *Wvh, *Woh, *Xh, *Xl, *QKh, *QKl, *Vth, *H;
    cudaGetSymbolAddress((void**)&Wqkh, g_Wqkh);
    cudaGetSymbolAddress((void**)&Wqkl, g_Wqkl);
    cudaGetSymbolAddress((void**)&Wvh,  g_Wvh);
    cudaGetSymbolAddress((void**)&Woh,  g_Woh);
    cudaGetSymbolAddress((void**)&Xh,   g_Xh);
    cudaGetSymbolAddress((void**)&Xl,   g_Xl);
    cudaGetSymbolAddress((void**)&QKh,  g_QKh);
    cudaGetSymbolAddress((void**)&QKl,  g_QKl);
    cudaGetSymbolAddress((void**)&Vth,  g_Vth);
    cudaGetSymbolAddress((void**)&H,    g_H);

    cudaFuncSetAttribute(hgemm, cudaFuncAttributeMaxDynamicSharedMemorySize,
                         GEMM_SMEM);
    cudaFuncSetAttribute(flash_attn, cudaFuncAttributeMaxDynamicSharedMemorySize,
                         FA_SMEM);

    // 1) fused weight prep + input conversion
    prep_w<<<dim3(2048, 6), 256>>>(Wqn, Wkn, Wqp, Wkp, Wvn, Wvp, Won, Wop,
                                   Wqkh, Wqkl, Wvh, Woh);
    cvt_pair<<<dim3(8192, 2), 256>>>(Xn, Xp, Xh, Xl);

    // 2) Q,K projections, 3-term, pair out, both streams (z)
    hgemm<<<dim3(8, 128, 2), 128, GEMM_SMEM>>>(
        Xh, Xl, Xh, 0, XSTR, 512,
        Wqkh, Wqkh, Wqkl, 0, WSTR, 512,
        QKh, QKl, 0, QKSTR, 1024, 512, 3, 4, 0);

    // 3) V transposed, 1-term, mode 7 (remap, halfoff = 64*z), both streams
    hgemm<<<dim3(128, 8, 2), 128, GEMM_SMEM>>>(
        Wvh, nullptr, nullptr, 0, WSTR, 512,
        Xh, nullptr, nullptr, 0, XSTR, 512,
        Vth, nullptr, 0, 0, ROWS, 512, 1, 7, 64);

    // 4) flash attention (FA2 register softmax), both streams (z)
    flash_attn<<<dim3(8, 128, 2), 256, FA_SMEM>>>(
        QKh, QKl, Vth, H, H + QKSTR);

    // 5) output projections, 1-term, fp32 out, both streams (z)
    hgemm<<<dim3(4, 128, 2), 128, GEMM_SMEM>>>(
        H, nullptr, nullptr, 0, HSTR, 1024,
        Woh, nullptr, nullptr, 0, WSTR, 1024,
        out, nullptr, 0, OSTR, 512, 1024, 1, 1, 0);
}